// round 14
// baseline (speedup 1.0000x reference)
#include <cuda_runtime.h>
#include <cuda_fp16.h>
#include <math.h>
#include <stdint.h>

typedef __half fp16;

#define Bq   8
#define Nq   2048
#define Dq   1024
#define Eq   16
#define Sq   64
#define ESq  1024
#define EPSq 1e-5f

// ---------------- scratch ----------------
__device__ __align__(16) float g_h  [(size_t)Bq * Eq * Sq * Dq];
__device__ __align__(16) float g_rowsum[(size_t)Bq * Nq];
__device__ __align__(16) float g_colsum[(size_t)Bq * ESq];

__device__ __align__(16) fp16 g_e16  [(size_t)Bq * Nq * ESq];   // exp(w) fp16
__device__ __align__(16) fp16 g_x16  [(size_t)Bq * Nq * Dq];
__device__ __align__(16) fp16 g_phi16[(size_t)Dq * ESq];
__device__ __align__(16) fp16 g_W116 [(size_t)Eq * Dq * Dq];
__device__ __align__(16) fp16 g_W216 [(size_t)Eq * Dq * Dq];
__device__ __align__(16) fp16 g_dspT [(size_t)Bq * ESq * Nq];
__device__ __align__(16) fp16 g_xin_h[(size_t)Bq * Eq * Sq * Dq], g_xin_l[(size_t)Bq * Eq * Sq * Dq];
__device__ __align__(16) fp16 g_x2_h [(size_t)Bq * Eq * Sq * Dq], g_x2_l [(size_t)Bq * Eq * Sq * Dq];
__device__ __align__(16) fp16 g_y16  [(size_t)Bq * Eq * Sq * Dq];
__device__ __align__(16) fp16 g_cmb  [(size_t)Bq * Nq * ESq];

// ===== mma.sync GEMM (R9 config): 256 thr, 2 CTA/SM, warp tile 64x32 =====
#define BM 128
#define BN 128
#define BK 64
#define NSTG 3
#define PA 144
#define PB 272
#define A_BYTES (128 * PA)
#define B_BYTES (64 * PB)
#define OFF_A 0
#define OFF_B A_BYTES
#define STAGE (A_BYTES + B_BYTES)
#define SMEM_DYN (NSTG * STAGE)       // 107520

__device__ __forceinline__ uint32_t s2u(const void* p) {
    uint32_t a;
    asm("{ .reg .u64 t; cvta.to.shared.u64 t, %1; cvt.u32.u64 %0, t; }" : "=r"(a) : "l"(p));
    return a;
}
__device__ __forceinline__ void cpa16(uint32_t dst, const void* src) {
    asm volatile("cp.async.cg.shared.global [%0], [%1], 16;" :: "r"(dst), "l"(src));
}
__device__ __forceinline__ void ldm_x4(uint32_t* r, uint32_t a) {
    asm volatile("ldmatrix.sync.aligned.m8n8.x4.shared.b16 {%0,%1,%2,%3}, [%4];"
                 : "=r"(r[0]), "=r"(r[1]), "=r"(r[2]), "=r"(r[3]) : "r"(a));
}
__device__ __forceinline__ void ldm_x4t(uint32_t* r, uint32_t a) {
    asm volatile("ldmatrix.sync.aligned.m8n8.x4.trans.shared.b16 {%0,%1,%2,%3}, [%4];"
                 : "=r"(r[0]), "=r"(r[1]), "=r"(r[2]), "=r"(r[3]) : "r"(a));
}
__device__ __forceinline__ void mma16816(float* c, const uint32_t* a, const uint32_t* b) {
    asm volatile(
        "mma.sync.aligned.m16n8k16.row.col.f32.f16.f16.f32 "
        "{%0,%1,%2,%3}, {%4,%5,%6,%7}, {%8,%9}, {%0,%1,%2,%3};"
        : "+f"(c[0]), "+f"(c[1]), "+f"(c[2]), "+f"(c[3])
        : "r"(a[0]), "r"(a[1]), "r"(a[2]), "r"(a[3]), "r"(b[0]), "r"(b[1]));
}

// EPI: 0 none, 1 +bias, 3 +bias+(resh+resl),
//      4 = exp: write fp16 exp(v) into Chb and accumulate rowsum/colsum atomics
// WC: write fp32 C.  SPLIT: 0 none, 1 fp16 hi+lo, 2 fp16 hi only.
template<int EPI, int WC, int SPLIT>
__global__ void __launch_bounds__(256, 2)
mma_gemm_k(const fp16* __restrict__ Ab, const fp16* __restrict__ Bb,
           const float* __restrict__ biasb,
           const fp16* __restrict__ reshb, const fp16* __restrict__ reslb,
           float* __restrict__ Cb, fp16* __restrict__ Chb, fp16* __restrict__ Clb,
           float* __restrict__ rowsumb, float* __restrict__ colsumb,
           int K, int lda, int ldb, int ldc,
           size_t sA, size_t sB, size_t sC, int bMod, size_t sBias,
           size_t aRowBlk, size_t cRowBlk)
{
    extern __shared__ char sm[];
    const uint32_t sb = s2u(sm);
    const int tid = threadIdx.x, wid = tid >> 5, lane = tid & 31;
    const int z = blockIdx.z;

    const fp16* A = Ab + (size_t)z * sA;
    const fp16* B = Bb + (size_t)(z % bMod) * sB;

    const int m0 = blockIdx.y * BM;
    const int n0 = blockIdx.x * BN;

    size_t aoff[4]; uint32_t adst[4];
#pragma unroll
    for (int i = 0; i < 4; i++) {
        const int idx = tid + i * 256;
        const int row = idx >> 3, kc = idx & 7;
        const int m = m0 + row;
        aoff[i] = ((size_t)(m >> 6)) * aRowBlk + (size_t)(m & 63) * lda + kc * 8;
        adst[i] = (uint32_t)(row * PA + kc * 16);
    }
    size_t boff[4]; uint32_t bdst[4];
#pragma unroll
    for (int i = 0; i < 4; i++) {
        const int idx = tid + i * 256;
        const int row = idx >> 4, nc = idx & 15;
        boff[i] = (size_t)row * ldb + n0 + nc * 8;
        bdst[i] = (uint32_t)(row * PB + nc * 16);
    }

    auto load_stage = [&](int t) {
        const uint32_t stg = sb + (t % NSTG) * STAGE;
        const size_t ke = (size_t)t * BK;
#pragma unroll
        for (int i = 0; i < 4; i++) cpa16(stg + OFF_A + adst[i], A + aoff[i] + ke);
        const size_t kb = ke * ldb;
#pragma unroll
        for (int i = 0; i < 4; i++) cpa16(stg + OFF_B + bdst[i], B + boff[i] + kb);
        asm volatile("cp.async.commit_group;" ::: "memory");
    };

    const int wm = (wid >> 2) * 64;
    const int wn = (wid & 3) * 32;

    float acc[4][4][4];
#pragma unroll
    for (int mi = 0; mi < 4; mi++)
#pragma unroll
        for (int ni = 0; ni < 4; ni++)
#pragma unroll
            for (int q = 0; q < 4; q++) acc[mi][ni][q] = 0.f;

    const int nt = K / BK;
    load_stage(0);
    if (nt > 1) load_stage(1);

    for (int t = 0; t < nt; t++) {
        if (t + 1 < nt) asm volatile("cp.async.wait_group 1;" ::: "memory");
        else            asm volatile("cp.async.wait_group 0;" ::: "memory");
        __syncthreads();
        if (t + 2 < nt) load_stage(t + 2);

        const uint32_t stg = sb + (t % NSTG) * STAGE;
#pragma unroll
        for (int ks = 0; ks < 4; ks++) {
            const int kb = ks * 16;
            uint32_t ah[4][4], bh[2][4];
#pragma unroll
            for (int mi = 0; mi < 4; mi++) {
                const uint32_t ao =
                    (uint32_t)((wm + mi * 16 + (lane & 15)) * PA + (kb + (lane >> 4) * 8) * 2);
                ldm_x4(ah[mi], stg + OFF_A + ao);
            }
#pragma unroll
            for (int nj = 0; nj < 2; nj++) {
                const uint32_t bo =
                    (uint32_t)((kb + (lane & 15)) * PB + (wn + nj * 16 + (lane >> 4) * 8) * 2);
                ldm_x4t(bh[nj], stg + OFF_B + bo);
            }
#pragma unroll
            for (int mi = 0; mi < 4; mi++)
#pragma unroll
                for (int ni = 0; ni < 4; ni++)
                    mma16816(acc[mi][ni], ah[mi], &bh[ni >> 1][(ni & 1) * 2]);
        }
    }

    // ---------------- epilogue ----------------
    float*       C  = WC ? (Cb + (size_t)z * sC) : nullptr;
    fp16*        Ch = (SPLIT || EPI == 4) ? (Chb + (size_t)z * sC) : nullptr;
    fp16*        Cl = (SPLIT == 1) ? (Clb + (size_t)z * sC) : nullptr;
    const float* bias = (EPI == 1 || EPI == 3) ? (biasb + (size_t)(z % bMod) * sBias) : nullptr;
    const fp16*  resh = (EPI == 3) ? (reshb + (size_t)z * sC) : nullptr;
    const fp16*  resl = (EPI == 3) ? (reslb + (size_t)z * sC) : nullptr;

    float rsumA[4], rsumB[4], csum[4][2];
    if (EPI == 4) {
#pragma unroll
        for (int mi = 0; mi < 4; mi++) { rsumA[mi] = 0.f; rsumB[mi] = 0.f; }
#pragma unroll
        for (int ni = 0; ni < 4; ni++) { csum[ni][0] = 0.f; csum[ni][1] = 0.f; }
    }

#pragma unroll
    for (int mi = 0; mi < 4; mi++) {
        const int mA = m0 + wm + mi * 16 + (lane >> 2);
        const int mB = mA + 8;
        const size_t coA = ((size_t)(mA >> 6)) * cRowBlk + (size_t)(mA & 63) * ldc;
        const size_t coB = ((size_t)(mB >> 6)) * cRowBlk + (size_t)(mB & 63) * ldc;
#pragma unroll
        for (int ni = 0; ni < 4; ni++) {
            const int col = n0 + wn + ni * 8 + (lane & 3) * 2;
            float2 v0 = make_float2(acc[mi][ni][0], acc[mi][ni][1]);
            float2 v1 = make_float2(acc[mi][ni][2], acc[mi][ni][3]);
            if (EPI == 1 || EPI == 3) {
                const float2 bb = *reinterpret_cast<const float2*>(&bias[col]);
                v0.x += bb.x; v0.y += bb.y; v1.x += bb.x; v1.y += bb.y;
            }
            if (EPI == 3) {
                const __half2 hA = *reinterpret_cast<const __half2*>(&resh[coA + col]);
                const __half2 lA = *reinterpret_cast<const __half2*>(&resl[coA + col]);
                const __half2 hB = *reinterpret_cast<const __half2*>(&resh[coB + col]);
                const __half2 lB = *reinterpret_cast<const __half2*>(&resl[coB + col]);
                v0.x += __half2float(hA.x) + __half2float(lA.x);
                v0.y += __half2float(hA.y) + __half2float(lA.y);
                v1.x += __half2float(hB.x) + __half2float(lB.x);
                v1.y += __half2float(hB.y) + __half2float(lB.y);
            }
            if (EPI == 4) {
                const float e0 = __expf(v0.x), e1 = __expf(v0.y);
                const float e2 = __expf(v1.x), e3 = __expf(v1.y);
                rsumA[mi] += e0 + e1;
                rsumB[mi] += e2 + e3;
                csum[ni][0] += e0 + e2;
                csum[ni][1] += e1 + e3;
                *reinterpret_cast<__half2*>(&Ch[coA + col]) =
                    __halves2half2(__float2half_rn(e0), __float2half_rn(e1));
                *reinterpret_cast<__half2*>(&Ch[coB + col]) =
                    __halves2half2(__float2half_rn(e2), __float2half_rn(e3));
            }
            if (WC) {
                *reinterpret_cast<float2*>(&C[coA + col]) = v0;
                *reinterpret_cast<float2*>(&C[coB + col]) = v1;
            }
            if (SPLIT) {
                fp16 h0 = __float2half_rn(v0.x), h1 = __float2half_rn(v0.y);
                fp16 h2 = __float2half_rn(v1.x), h3 = __float2half_rn(v1.y);
                *reinterpret_cast<__half2*>(&Ch[coA + col]) = __halves2half2(h0, h1);
                *reinterpret_cast<__half2*>(&Ch[coB + col]) = __halves2half2(h2, h3);
                if (SPLIT == 1) {
                    *reinterpret_cast<__half2*>(&Cl[coA + col]) = __halves2half2(
                        __float2half_rn(v0.x - __half2float(h0)),
                        __float2half_rn(v0.y - __half2float(h1)));
                    *reinterpret_cast<__half2*>(&Cl[coB + col]) = __halves2half2(
                        __float2half_rn(v1.x - __half2float(h2)),
                        __float2half_rn(v1.y - __half2float(h3)));
                }
            }
        }
    }

    if (EPI == 4) {
        float* rowsum = rowsumb + (size_t)z * Nq;
        float* colsum = colsumb + (size_t)z * ESq;
#pragma unroll
        for (int mi = 0; mi < 4; mi++) {
            float ra = rsumA[mi], rb = rsumB[mi];
            ra += __shfl_xor_sync(0xffffffffu, ra, 1);
            ra += __shfl_xor_sync(0xffffffffu, ra, 2);
            rb += __shfl_xor_sync(0xffffffffu, rb, 1);
            rb += __shfl_xor_sync(0xffffffffu, rb, 2);
            if ((lane & 3) == 0) {
                const int mA = m0 + wm + mi * 16 + (lane >> 2);
                atomicAdd(&rowsum[mA], ra);
                atomicAdd(&rowsum[mA + 8], rb);
            }
        }
#pragma unroll
        for (int ni = 0; ni < 4; ni++) {
            float c0 = csum[ni][0], c1 = csum[ni][1];
            c0 += __shfl_xor_sync(0xffffffffu, c0, 4);
            c0 += __shfl_xor_sync(0xffffffffu, c0, 8);
            c0 += __shfl_xor_sync(0xffffffffu, c0, 16);
            c1 += __shfl_xor_sync(0xffffffffu, c1, 4);
            c1 += __shfl_xor_sync(0xffffffffu, c1, 8);
            c1 += __shfl_xor_sync(0xffffffffu, c1, 16);
            if ((lane >> 2) == 0) {
                const int col = n0 + wn + ni * 8 + (lane & 3) * 2;
                atomicAdd(&colsum[col], c0);
                atomicAdd(&colsum[col + 1], c1);
            }
        }
    }
}

// ====== conversions ======
#define N4_X   ((size_t)Bq * Nq * Dq / 4)
#define N4_PHI ((size_t)Dq * ESq / 4)
#define N4_W   ((size_t)Eq * Dq * Dq / 4)

__global__ void convert_xphi_k(const float* __restrict__ x, const float* __restrict__ phi,
                               fp16* __restrict__ ox, fp16* __restrict__ ophi)
{
    size_t i = (size_t)blockIdx.x * blockDim.x + threadIdx.x;
    if (i >= N4_X + N4_PHI) return;
    const float* in; fp16* o;
    if (i < N4_X) { in = x; o = ox; }
    else          { i -= N4_X; in = phi; o = ophi; }
    const float4 v = reinterpret_cast<const float4*>(in)[i];
    reinterpret_cast<__half2*>(o)[2 * i] =
        __halves2half2(__float2half_rn(v.x), __float2half_rn(v.y));
    reinterpret_cast<__half2*>(o)[2 * i + 1] =
        __halves2half2(__float2half_rn(v.z), __float2half_rn(v.w));
}

__global__ void convert_W_k(const float* __restrict__ W1, const float* __restrict__ W2,
                            fp16* __restrict__ oW1, fp16* __restrict__ oW2)
{
    size_t i = (size_t)blockIdx.x * blockDim.x + threadIdx.x;
    if (i >= 2 * N4_W) return;
    const float* in; fp16* o;
    if (i < N4_W) { in = W1; o = oW1; }
    else          { i -= N4_W; in = W2; o = oW2; }
    const float4 v = reinterpret_cast<const float4*>(in)[i];
    reinterpret_cast<__half2*>(o)[2 * i] =
        __halves2half2(__float2half_rn(v.x), __float2half_rn(v.y));
    reinterpret_cast<__half2*>(o)[2 * i + 1] =
        __halves2half2(__float2half_rn(v.z), __float2half_rn(v.w));
}

// ====== fused dispatch+combine: read e16 once; write dspT (transposed) + cmb ======
__global__ void softmax_both_k(const fp16* __restrict__ e16,
                               const float* __restrict__ colsum,
                               const float* __restrict__ rowsum,
                               fp16* __restrict__ dspT, fp16* __restrict__ cmb)
{
    const int b = blockIdx.y, lane = threadIdx.x & 31, grp = threadIdx.x >> 5;
    const int col0 = blockIdx.x * 32;
    const fp16* p = e16 + (size_t)b * Nq * ESq + col0;
    fp16* cm = cmb + (size_t)b * Nq * ESq + col0;

    __shared__ float icol[32], irow[32];
    __shared__ float t[32][33];

    if (threadIdx.x < 32)
        icol[threadIdx.x] = 1.f / colsum[(size_t)b * ESq + col0 + threadIdx.x];
    __syncthreads();

    const size_t obase = (size_t)b * ESq * Nq;
    for (int n0 = 0; n0 < Nq; n0 += 32) {
        if (threadIdx.x < 32)
            irow[threadIdx.x] = 1.f / rowsum[(size_t)b * Nq + n0 + threadIdx.x];
        __syncthreads();
#pragma unroll
        for (int i = 0; i < 4; i++) {
            const int r = grp * 4 + i;
            const float e = __half2float(p[(size_t)(n0 + r) * ESq + lane]);
            t[r][lane] = e;
            cm[(size_t)(n0 + r) * ESq + lane] = __float2half_rn(e * irow[r]);
        }
        __syncthreads();
#pragma unroll
        for (int i = 0; i < 4; i++) {
            const int cc = grp * 4 + i;
            dspT[obase + (size_t)(col0 + cc) * Nq + n0 + lane] =
                __float2half_rn(t[lane][cc] * icol[cc]);
        }
        __syncthreads();
    }
}

// ===== LN + relu + residual =====
__global__ void ln_relu_k(const float* __restrict__ h,
                          const fp16* __restrict__ xh, const fp16* __restrict__ xl,
                          const float* __restrict__ g, const float* __restrict__ be,
                          fp16* __restrict__ oh, fp16* __restrict__ ol)
{
    const int r = blockIdx.x;
    const int e = (r / Sq) % Eq;
    const float* hr = h + (size_t)r * Dq;
    const int tid = threadIdx.x;
    __shared__ float rs[256], rs2[256];

    float v[4];
    float s = 0.f, s2 = 0.f;
#pragma unroll
    for (int j = 0; j < 4; j++) {
        v[j] = hr[tid + 256 * j];
        s += v[j]; s2 += v[j] * v[j];
    }
    rs[tid] = s; rs2[tid] = s2;
    __syncthreads();
    for (int off = 128; off > 0; off >>= 1) {
        if (tid < off) { rs[tid] += rs[tid + off]; rs2[tid] += rs2[tid + off]; }
        __syncthreads();
    }
    const float mean = rs[0] * (1.f / Dq);
    const float var  = rs2[0] * (1.f / Dq) - mean * mean;
    const float rstd = rsqrtf(var + EPSq);

#pragma unroll
    for (int j = 0; j < 4; j++) {
        const int d = tid + 256 * j;
        const size_t o = (size_t)r * Dq + d;
        const float xr = __half2float(xh[o]) + __half2float(xl[o]);
        const float ln = (v[j] - mean) * rstd * g[(size_t)e * Dq + d] + be[(size_t)e * Dq + d];
        const float val = xr + fmaxf(ln, 0.f);
        fp16 hh = __float2half_rn(val);
        oh[o] = hh;
        ol[o] = __float2half_rn(val - __half2float(hh));
    }
}

// ================= launch =================
extern "C" void kernel_launch(void* const* d_in, const int* in_sizes, int n_in,
                              void* d_out, int out_size)
{
    const float* x   = (const float*)d_in[0];
    const float* phi = (const float*)d_in[1];
    const float* W1  = (const float*)d_in[2];
    const float* b1  = (const float*)d_in[3];
    const float* g1  = (const float*)d_in[4];
    const float* be1 = (const float*)d_in[5];
    const float* W2  = (const float*)d_in[6];
    const float* b2  = (const float*)d_in[7];
    float* out = (float*)d_out;

    static cudaStream_t s_side = nullptr;
    static cudaEvent_t eFork = nullptr, eW = nullptr;
    if (s_side == nullptr) {
        cudaStreamCreateWithFlags(&s_side, cudaStreamNonBlocking);
        cudaEventCreateWithFlags(&eFork, cudaEventDisableTiming);
        cudaEventCreateWithFlags(&eW,    cudaEventDisableTiming);
        cudaFuncSetAttribute(mma_gemm_k<4,0,0>, cudaFuncAttributeMaxDynamicSharedMemorySize, SMEM_DYN);
        cudaFuncSetAttribute(mma_gemm_k<0,0,1>, cudaFuncAttributeMaxDynamicSharedMemorySize, SMEM_DYN);
        cudaFuncSetAttribute(mma_gemm_k<1,1,0>, cudaFuncAttributeMaxDynamicSharedMemorySize, SMEM_DYN);
        cudaFuncSetAttribute(mma_gemm_k<3,0,2>, cudaFuncAttributeMaxDynamicSharedMemorySize, SMEM_DYN);
        cudaFuncSetAttribute(mma_gemm_k<0,1,0>, cudaFuncAttributeMaxDynamicSharedMemorySize, SMEM_DYN);
    }

    float *h, *rowsum, *colsum;
    cudaGetSymbolAddress((void**)&h, g_h);
    cudaGetSymbolAddress((void**)&rowsum, g_rowsum);
    cudaGetSymbolAddress((void**)&colsum, g_colsum);

    fp16 *e16,*x16,*phi16,*W116,*W216,*dspT,*xin_h,*xin_l,*x2_h,*x2_l,*y16,*cmb;
    cudaGetSymbolAddress((void**)&e16, g_e16);
    cudaGetSymbolAddress((void**)&x16, g_x16);
    cudaGetSymbolAddress((void**)&phi16, g_phi16);
    cudaGetSymbolAddress((void**)&W116, g_W116);
    cudaGetSymbolAddress((void**)&W216, g_W216);
    cudaGetSymbolAddress((void**)&dspT, g_dspT);
    cudaGetSymbolAddress((void**)&xin_h, g_xin_h); cudaGetSymbolAddress((void**)&xin_l, g_xin_l);
    cudaGetSymbolAddress((void**)&x2_h, g_x2_h);   cudaGetSymbolAddress((void**)&x2_l, g_x2_l);
    cudaGetSymbolAddress((void**)&y16, g_y16);
    cudaGetSymbolAddress((void**)&cmb, g_cmb);

    const size_t EXP = (size_t)Eq * Sq * Dq;

    // fork side stream: W conversion (needed first by K4)
    cudaEventRecord(eFork, 0);
    cudaStreamWaitEvent(s_side, eFork, 0);
    convert_W_k<<<(int)((2 * N4_W + 255) / 256), 256, 0, s_side>>>(W1, W2, W116, W216);
    cudaEventRecord(eW, s_side);

    // main: zero denominators, convert x/phi, K1 (exp epilogue)
    cudaMemsetAsync(rowsum, 0, (size_t)Bq * Nq * sizeof(float), 0);
    cudaMemsetAsync(colsum, 0, (size_t)Bq * ESq * sizeof(float), 0);
    convert_xphi_k<<<(int)((N4_X + N4_PHI + 255) / 256), 256>>>(x, phi, x16, phi16);

    mma_gemm_k<4,0,0><<<dim3(ESq/BN, Nq/BM, Bq), 256, SMEM_DYN>>>(
        x16, phi16, nullptr, nullptr, nullptr, nullptr, e16, nullptr,
        rowsum, colsum,
        Dq, Dq, ESq, ESq,
        (size_t)Nq*Dq, 0, (size_t)Nq*ESq, 1, 0,
        (size_t)64*Dq, (size_t)64*ESq);

    // fused dispatch+combine (single read of e16)
    softmax_both_k<<<dim3(ESq/32, Bq), 256>>>(e16, colsum, rowsum, dspT, cmb);

    // K3: xin[b] = dsp[b]^T @ x[b]
    mma_gemm_k<0,0,1><<<dim3(Dq/BN, ESq/BM, Bq), 256, SMEM_DYN>>>(
        dspT, x16, nullptr, nullptr, nullptr, nullptr, xin_h, xin_l,
        nullptr, nullptr,
        Nq, Nq, Dq, Dq,
        (size_t)ESq*Nq, (size_t)Nq*Dq, (size_t)ESq*Dq, Bq, 0,
        (size_t)64*Nq, (size_t)64*Dq);

    cudaStreamWaitEvent(0, eW, 0);

    // K4
    mma_gemm_k<1,1,0><<<dim3(Dq/BN, (Bq*Sq)/BM, Eq), 256, SMEM_DYN>>>(
        xin_h, W116, b1, nullptr, nullptr, h, nullptr, nullptr,
        nullptr, nullptr,
        Dq, Dq, Dq, Dq,
        (size_t)Sq*Dq, (size_t)Dq*Dq, (size_t)Sq*Dq, Eq, (size_t)Dq,
        EXP, EXP);

    ln_relu_k<<<Bq*Eq*Sq, 256>>>(h, xin_h, xin_l, g1, be1, x2_h, x2_l);

    // K6 -> fp16 y
    mma_gemm_k<3,0,2><<<dim3(Dq/BN, (Bq*Sq)/BM, Eq), 256, SMEM_DYN>>>(
        x2_h, W216, b2, x2_h, x2_l, nullptr, y16, nullptr,
        nullptr, nullptr,
        Dq, Dq, Dq, Dq,
        (size_t)Sq*Dq, (size_t)Dq*Dq, (size_t)Sq*Dq, Eq, (size_t)Dq,
        EXP, EXP);

    // K8
    mma_gemm_k<0,1,0><<<dim3(Dq/BN, Nq/BM, Bq), 256, SMEM_DYN>>>(
        cmb, y16, nullptr, nullptr, nullptr, out, nullptr, nullptr,
        nullptr, nullptr,
        ESq, ESq, Dq, Dq,
        (size_t)Nq*ESq, EXP, (size_t)Nq*Dq, Bq, 0,
        (size_t)64*ESq, (size_t)64*Dq);
}

// round 15
// speedup vs baseline: 1.0893x; 1.0893x over previous
#include <cuda_runtime.h>
#include <cuda_fp16.h>
#include <math.h>
#include <stdint.h>

typedef __half fp16;

#define Bq   8
#define Nq   2048
#define Dq   1024
#define Eq   16
#define Sq   64
#define ESq  1024
#define EPSq 1e-5f

// ---------------- scratch ----------------
__device__ __align__(16) float g_h  [(size_t)Bq * Eq * Sq * Dq];
__device__ __align__(16) float g_rowsum[(size_t)Bq * Nq];
__device__ __align__(16) float g_colsum[(size_t)Bq * ESq];

__device__ __align__(16) fp16 g_e16  [(size_t)Bq * Nq * ESq];   // exp(w) fp16
__device__ __align__(16) fp16 g_x16  [(size_t)Bq * Nq * Dq];
__device__ __align__(16) fp16 g_phi16[(size_t)Dq * ESq];
__device__ __align__(16) fp16 g_W116 [(size_t)Eq * Dq * Dq];
__device__ __align__(16) fp16 g_W216 [(size_t)Eq * Dq * Dq];
__device__ __align__(16) fp16 g_dspT [(size_t)Bq * ESq * Nq];
__device__ __align__(16) fp16 g_xin_h[(size_t)Bq * Eq * Sq * Dq], g_xin_l[(size_t)Bq * Eq * Sq * Dq];
__device__ __align__(16) fp16 g_x2_h [(size_t)Bq * Eq * Sq * Dq], g_x2_l [(size_t)Bq * Eq * Sq * Dq];
__device__ __align__(16) fp16 g_y16  [(size_t)Bq * Eq * Sq * Dq];
__device__ __align__(16) fp16 g_cmb  [(size_t)Bq * Nq * ESq];

// ===== mma.sync GEMM (R9 config): 256 thr, 2 CTA/SM, warp tile 64x32 =====
#define BM 128
#define BN 128
#define BK 64
#define NSTG 3
#define PA 144
#define PB 272
#define A_BYTES (128 * PA)
#define B_BYTES (64 * PB)
#define OFF_A 0
#define OFF_B A_BYTES
#define STAGE (A_BYTES + B_BYTES)
#define SMEM_DYN (NSTG * STAGE)       // 107520

__device__ __forceinline__ uint32_t s2u(const void* p) {
    uint32_t a;
    asm("{ .reg .u64 t; cvta.to.shared.u64 t, %1; cvt.u32.u64 %0, t; }" : "=r"(a) : "l"(p));
    return a;
}
__device__ __forceinline__ void cpa16(uint32_t dst, const void* src) {
    asm volatile("cp.async.cg.shared.global [%0], [%1], 16;" :: "r"(dst), "l"(src));
}
__device__ __forceinline__ void ldm_x4(uint32_t* r, uint32_t a) {
    asm volatile("ldmatrix.sync.aligned.m8n8.x4.shared.b16 {%0,%1,%2,%3}, [%4];"
                 : "=r"(r[0]), "=r"(r[1]), "=r"(r[2]), "=r"(r[3]) : "r"(a));
}
__device__ __forceinline__ void ldm_x4t(uint32_t* r, uint32_t a) {
    asm volatile("ldmatrix.sync.aligned.m8n8.x4.trans.shared.b16 {%0,%1,%2,%3}, [%4];"
                 : "=r"(r[0]), "=r"(r[1]), "=r"(r[2]), "=r"(r[3]) : "r"(a));
}
__device__ __forceinline__ void mma16816(float* c, const uint32_t* a, const uint32_t* b) {
    asm volatile(
        "mma.sync.aligned.m16n8k16.row.col.f32.f16.f16.f32 "
        "{%0,%1,%2,%3}, {%4,%5,%6,%7}, {%8,%9}, {%0,%1,%2,%3};"
        : "+f"(c[0]), "+f"(c[1]), "+f"(c[2]), "+f"(c[3])
        : "r"(a[0]), "r"(a[1]), "r"(a[2]), "r"(a[3]), "r"(b[0]), "r"(b[1]));
}

// EPI: 0 none, 1 +bias, 3 +bias+(resh+resl),
//      4 = exp: write fp16 exp(v) into Chb and accumulate rowsum/colsum atomics
// WC: write fp32 C.  SPLIT: 0 none, 1 fp16 hi+lo, 2 fp16 hi only.
template<int EPI, int WC, int SPLIT>
__global__ void __launch_bounds__(256, 2)
mma_gemm_k(const fp16* __restrict__ Ab, const fp16* __restrict__ Bb,
           const float* __restrict__ biasb,
           const fp16* __restrict__ reshb, const fp16* __restrict__ reslb,
           float* __restrict__ Cb, fp16* __restrict__ Chb, fp16* __restrict__ Clb,
           float* __restrict__ rowsumb, float* __restrict__ colsumb,
           int K, int lda, int ldb, int ldc,
           size_t sA, size_t sB, size_t sC, int bMod, size_t sBias,
           size_t aRowBlk, size_t cRowBlk)
{
    extern __shared__ char sm[];
    const uint32_t sb = s2u(sm);
    const int tid = threadIdx.x, wid = tid >> 5, lane = tid & 31;
    const int z = blockIdx.z;

    const fp16* A = Ab + (size_t)z * sA;
    const fp16* B = Bb + (size_t)(z % bMod) * sB;

    const int m0 = blockIdx.y * BM;
    const int n0 = blockIdx.x * BN;

    size_t aoff[4]; uint32_t adst[4];
#pragma unroll
    for (int i = 0; i < 4; i++) {
        const int idx = tid + i * 256;
        const int row = idx >> 3, kc = idx & 7;
        const int m = m0 + row;
        aoff[i] = ((size_t)(m >> 6)) * aRowBlk + (size_t)(m & 63) * lda + kc * 8;
        adst[i] = (uint32_t)(row * PA + kc * 16);
    }
    size_t boff[4]; uint32_t bdst[4];
#pragma unroll
    for (int i = 0; i < 4; i++) {
        const int idx = tid + i * 256;
        const int row = idx >> 4, nc = idx & 15;
        boff[i] = (size_t)row * ldb + n0 + nc * 8;
        bdst[i] = (uint32_t)(row * PB + nc * 16);
    }

    auto load_stage = [&](int t) {
        const uint32_t stg = sb + (t % NSTG) * STAGE;
        const size_t ke = (size_t)t * BK;
#pragma unroll
        for (int i = 0; i < 4; i++) cpa16(stg + OFF_A + adst[i], A + aoff[i] + ke);
        const size_t kb = ke * ldb;
#pragma unroll
        for (int i = 0; i < 4; i++) cpa16(stg + OFF_B + bdst[i], B + boff[i] + kb);
        asm volatile("cp.async.commit_group;" ::: "memory");
    };

    const int wm = (wid >> 2) * 64;
    const int wn = (wid & 3) * 32;

    float acc[4][4][4];
#pragma unroll
    for (int mi = 0; mi < 4; mi++)
#pragma unroll
        for (int ni = 0; ni < 4; ni++)
#pragma unroll
            for (int q = 0; q < 4; q++) acc[mi][ni][q] = 0.f;

    const int nt = K / BK;
    load_stage(0);
    if (nt > 1) load_stage(1);

    for (int t = 0; t < nt; t++) {
        if (t + 1 < nt) asm volatile("cp.async.wait_group 1;" ::: "memory");
        else            asm volatile("cp.async.wait_group 0;" ::: "memory");
        __syncthreads();
        if (t + 2 < nt) load_stage(t + 2);

        const uint32_t stg = sb + (t % NSTG) * STAGE;
#pragma unroll
        for (int ks = 0; ks < 4; ks++) {
            const int kb = ks * 16;
            uint32_t ah[4][4], bh[2][4];
#pragma unroll
            for (int mi = 0; mi < 4; mi++) {
                const uint32_t ao =
                    (uint32_t)((wm + mi * 16 + (lane & 15)) * PA + (kb + (lane >> 4) * 8) * 2);
                ldm_x4(ah[mi], stg + OFF_A + ao);
            }
#pragma unroll
            for (int nj = 0; nj < 2; nj++) {
                const uint32_t bo =
                    (uint32_t)((kb + (lane & 15)) * PB + (wn + nj * 16 + (lane >> 4) * 8) * 2);
                ldm_x4t(bh[nj], stg + OFF_B + bo);
            }
#pragma unroll
            for (int mi = 0; mi < 4; mi++)
#pragma unroll
                for (int ni = 0; ni < 4; ni++)
                    mma16816(acc[mi][ni], ah[mi], &bh[ni >> 1][(ni & 1) * 2]);
        }
    }

    // ---------------- epilogue ----------------
    float*       C  = WC ? (Cb + (size_t)z * sC) : nullptr;
    fp16*        Ch = (SPLIT || EPI == 4) ? (Chb + (size_t)z * sC) : nullptr;
    fp16*        Cl = (SPLIT == 1) ? (Clb + (size_t)z * sC) : nullptr;
    const float* bias = (EPI == 1 || EPI == 3) ? (biasb + (size_t)(z % bMod) * sBias) : nullptr;
    const fp16*  resh = (EPI == 3) ? (reshb + (size_t)z * sC) : nullptr;
    const fp16*  resl = (EPI == 3) ? (reslb + (size_t)z * sC) : nullptr;

    float rsumA[4], rsumB[4], csum[4][2];
    if (EPI == 4) {
#pragma unroll
        for (int mi = 0; mi < 4; mi++) { rsumA[mi] = 0.f; rsumB[mi] = 0.f; }
#pragma unroll
        for (int ni = 0; ni < 4; ni++) { csum[ni][0] = 0.f; csum[ni][1] = 0.f; }
    }

#pragma unroll
    for (int mi = 0; mi < 4; mi++) {
        const int mA = m0 + wm + mi * 16 + (lane >> 2);
        const int mB = mA + 8;
        const size_t coA = ((size_t)(mA >> 6)) * cRowBlk + (size_t)(mA & 63) * ldc;
        const size_t coB = ((size_t)(mB >> 6)) * cRowBlk + (size_t)(mB & 63) * ldc;
#pragma unroll
        for (int ni = 0; ni < 4; ni++) {
            const int col = n0 + wn + ni * 8 + (lane & 3) * 2;
            float2 v0 = make_float2(acc[mi][ni][0], acc[mi][ni][1]);
            float2 v1 = make_float2(acc[mi][ni][2], acc[mi][ni][3]);
            if (EPI == 1 || EPI == 3) {
                const float2 bb = *reinterpret_cast<const float2*>(&bias[col]);
                v0.x += bb.x; v0.y += bb.y; v1.x += bb.x; v1.y += bb.y;
            }
            if (EPI == 3) {
                const __half2 hA = *reinterpret_cast<const __half2*>(&resh[coA + col]);
                const __half2 lA = *reinterpret_cast<const __half2*>(&resl[coA + col]);
                const __half2 hB = *reinterpret_cast<const __half2*>(&resh[coB + col]);
                const __half2 lB = *reinterpret_cast<const __half2*>(&resl[coB + col]);
                v0.x += __half2float(hA.x) + __half2float(lA.x);
                v0.y += __half2float(hA.y) + __half2float(lA.y);
                v1.x += __half2float(hB.x) + __half2float(lB.x);
                v1.y += __half2float(hB.y) + __half2float(lB.y);
            }
            if (EPI == 4) {
                const float e0 = __expf(v0.x), e1 = __expf(v0.y);
                const float e2 = __expf(v1.x), e3 = __expf(v1.y);
                rsumA[mi] += e0 + e1;
                rsumB[mi] += e2 + e3;
                csum[ni][0] += e0 + e2;
                csum[ni][1] += e1 + e3;
                *reinterpret_cast<__half2*>(&Ch[coA + col]) =
                    __halves2half2(__float2half_rn(e0), __float2half_rn(e1));
                *reinterpret_cast<__half2*>(&Ch[coB + col]) =
                    __halves2half2(__float2half_rn(e2), __float2half_rn(e3));
            }
            if (WC) {
                *reinterpret_cast<float2*>(&C[coA + col]) = v0;
                *reinterpret_cast<float2*>(&C[coB + col]) = v1;
            }
            if (SPLIT) {
                fp16 h0 = __float2half_rn(v0.x), h1 = __float2half_rn(v0.y);
                fp16 h2 = __float2half_rn(v1.x), h3 = __float2half_rn(v1.y);
                *reinterpret_cast<__half2*>(&Ch[coA + col]) = __halves2half2(h0, h1);
                *reinterpret_cast<__half2*>(&Ch[coB + col]) = __halves2half2(h2, h3);
                if (SPLIT == 1) {
                    *reinterpret_cast<__half2*>(&Cl[coA + col]) = __halves2half2(
                        __float2half_rn(v0.x - __half2float(h0)),
                        __float2half_rn(v0.y - __half2float(h1)));
                    *reinterpret_cast<__half2*>(&Cl[coB + col]) = __halves2half2(
                        __float2half_rn(v1.x - __half2float(h2)),
                        __float2half_rn(v1.y - __half2float(h3)));
                }
            }
        }
    }

    if (EPI == 4) {
        float* rowsum = rowsumb + (size_t)z * Nq;
        float* colsum = colsumb + (size_t)z * ESq;
#pragma unroll
        for (int mi = 0; mi < 4; mi++) {
            float ra = rsumA[mi], rb = rsumB[mi];
            ra += __shfl_xor_sync(0xffffffffu, ra, 1);
            ra += __shfl_xor_sync(0xffffffffu, ra, 2);
            rb += __shfl_xor_sync(0xffffffffu, rb, 1);
            rb += __shfl_xor_sync(0xffffffffu, rb, 2);
            if ((lane & 3) == 0) {
                const int mA = m0 + wm + mi * 16 + (lane >> 2);
                atomicAdd(&rowsum[mA], ra);
                atomicAdd(&rowsum[mA + 8], rb);
            }
        }
#pragma unroll
        for (int ni = 0; ni < 4; ni++) {
            float c0 = csum[ni][0], c1 = csum[ni][1];
            c0 += __shfl_xor_sync(0xffffffffu, c0, 4);
            c0 += __shfl_xor_sync(0xffffffffu, c0, 8);
            c0 += __shfl_xor_sync(0xffffffffu, c0, 16);
            c1 += __shfl_xor_sync(0xffffffffu, c1, 4);
            c1 += __shfl_xor_sync(0xffffffffu, c1, 8);
            c1 += __shfl_xor_sync(0xffffffffu, c1, 16);
            if ((lane >> 2) == 0) {
                const int col = n0 + wn + ni * 8 + (lane & 3) * 2;
                atomicAdd(&colsum[col], c0);
                atomicAdd(&colsum[col + 1], c1);
            }
        }
    }
}

// ====== conversions ======
#define N4_X   ((size_t)Bq * Nq * Dq / 4)
#define N4_PHI ((size_t)Dq * ESq / 4)
#define N4_W   ((size_t)Eq * Dq * Dq / 4)

__global__ void convert_xphi_k(const float* __restrict__ x, const float* __restrict__ phi,
                               fp16* __restrict__ ox, fp16* __restrict__ ophi)
{
    size_t i = (size_t)blockIdx.x * blockDim.x + threadIdx.x;
    if (i >= N4_X + N4_PHI) return;
    const float* in; fp16* o;
    if (i < N4_X) { in = x; o = ox; }
    else          { i -= N4_X; in = phi; o = ophi; }
    const float4 v = reinterpret_cast<const float4*>(in)[i];
    reinterpret_cast<__half2*>(o)[2 * i] =
        __halves2half2(__float2half_rn(v.x), __float2half_rn(v.y));
    reinterpret_cast<__half2*>(o)[2 * i + 1] =
        __halves2half2(__float2half_rn(v.z), __float2half_rn(v.w));
}

__global__ void convert_W_k(const float* __restrict__ W1, const float* __restrict__ W2,
                            fp16* __restrict__ oW1, fp16* __restrict__ oW2)
{
    size_t i = (size_t)blockIdx.x * blockDim.x + threadIdx.x;
    if (i >= 2 * N4_W) return;
    const float* in; fp16* o;
    if (i < N4_W) { in = W1; o = oW1; }
    else          { i -= N4_W; in = W2; o = oW2; }
    const float4 v = reinterpret_cast<const float4*>(in)[i];
    reinterpret_cast<__half2*>(o)[2 * i] =
        __halves2half2(__float2half_rn(v.x), __float2half_rn(v.y));
    reinterpret_cast<__half2*>(o)[2 * i + 1] =
        __halves2half2(__float2half_rn(v.z), __float2half_rn(v.w));
}

// ====== fused dispatch+combine, token-partitioned for parallelism ======
// grid: (ESq/32, Nq/256, Bq); each block: 32 cols x 256 tokens
__global__ void softmax_both_k(const fp16* __restrict__ e16,
                               const float* __restrict__ colsum,
                               const float* __restrict__ rowsum,
                               fp16* __restrict__ dspT, fp16* __restrict__ cmb)
{
    const int b = blockIdx.z, lane = threadIdx.x & 31, grp = threadIdx.x >> 5;
    const int col0 = blockIdx.x * 32;
    const int nbase = blockIdx.y * 256;
    const fp16* p = e16 + (size_t)b * Nq * ESq + col0;
    fp16* cm = cmb + (size_t)b * Nq * ESq + col0;

    __shared__ float icol[32];
    __shared__ float irow[256];
    __shared__ float t[32][33];

    if (threadIdx.x < 32)
        icol[threadIdx.x] = 1.f / colsum[(size_t)b * ESq + col0 + threadIdx.x];
    irow[threadIdx.x] = 1.f / rowsum[(size_t)b * Nq + nbase + threadIdx.x];
    __syncthreads();

    const size_t obase = (size_t)b * ESq * Nq;
    for (int nc = 0; nc < 256; nc += 32) {
        const int n0 = nbase + nc;
#pragma unroll
        for (int i = 0; i < 4; i++) {
            const int r = grp * 4 + i;
            const float e = __half2float(p[(size_t)(n0 + r) * ESq + lane]);
            t[r][lane] = e;
            cm[(size_t)(n0 + r) * ESq + lane] = __float2half_rn(e * irow[nc + r]);
        }
        __syncthreads();
#pragma unroll
        for (int i = 0; i < 4; i++) {
            const int cc = grp * 4 + i;
            dspT[obase + (size_t)(col0 + cc) * Nq + n0 + lane] =
                __float2half_rn(t[lane][cc] * icol[cc]);
        }
        __syncthreads();
    }
}

// ===== LN + relu + residual =====
__global__ void ln_relu_k(const float* __restrict__ h,
                          const fp16* __restrict__ xh, const fp16* __restrict__ xl,
                          const float* __restrict__ g, const float* __restrict__ be,
                          fp16* __restrict__ oh, fp16* __restrict__ ol)
{
    const int r = blockIdx.x;
    const int e = (r / Sq) % Eq;
    const float* hr = h + (size_t)r * Dq;
    const int tid = threadIdx.x;
    __shared__ float rs[256], rs2[256];

    float v[4];
    float s = 0.f, s2 = 0.f;
#pragma unroll
    for (int j = 0; j < 4; j++) {
        v[j] = hr[tid + 256 * j];
        s += v[j]; s2 += v[j] * v[j];
    }
    rs[tid] = s; rs2[tid] = s2;
    __syncthreads();
    for (int off = 128; off > 0; off >>= 1) {
        if (tid < off) { rs[tid] += rs[tid + off]; rs2[tid] += rs2[tid + off]; }
        __syncthreads();
    }
    const float mean = rs[0] * (1.f / Dq);
    const float var  = rs2[0] * (1.f / Dq) - mean * mean;
    const float rstd = rsqrtf(var + EPSq);

#pragma unroll
    for (int j = 0; j < 4; j++) {
        const int d = tid + 256 * j;
        const size_t o = (size_t)r * Dq + d;
        const float xr = __half2float(xh[o]) + __half2float(xl[o]);
        const float ln = (v[j] - mean) * rstd * g[(size_t)e * Dq + d] + be[(size_t)e * Dq + d];
        const float val = xr + fmaxf(ln, 0.f);
        fp16 hh = __float2half_rn(val);
        oh[o] = hh;
        ol[o] = __float2half_rn(val - __half2float(hh));
    }
}

// ================= launch =================
extern "C" void kernel_launch(void* const* d_in, const int* in_sizes, int n_in,
                              void* d_out, int out_size)
{
    const float* x   = (const float*)d_in[0];
    const float* phi = (const float*)d_in[1];
    const float* W1  = (const float*)d_in[2];
    const float* b1  = (const float*)d_in[3];
    const float* g1  = (const float*)d_in[4];
    const float* be1 = (const float*)d_in[5];
    const float* W2  = (const float*)d_in[6];
    const float* b2  = (const float*)d_in[7];
    float* out = (float*)d_out;

    static cudaStream_t s_side = nullptr;
    static cudaEvent_t eFork = nullptr, eW = nullptr;
    if (s_side == nullptr) {
        cudaStreamCreateWithFlags(&s_side, cudaStreamNonBlocking);
        cudaEventCreateWithFlags(&eFork, cudaEventDisableTiming);
        cudaEventCreateWithFlags(&eW,    cudaEventDisableTiming);
        cudaFuncSetAttribute(mma_gemm_k<4,0,0>, cudaFuncAttributeMaxDynamicSharedMemorySize, SMEM_DYN);
        cudaFuncSetAttribute(mma_gemm_k<0,0,1>, cudaFuncAttributeMaxDynamicSharedMemorySize, SMEM_DYN);
        cudaFuncSetAttribute(mma_gemm_k<1,1,0>, cudaFuncAttributeMaxDynamicSharedMemorySize, SMEM_DYN);
        cudaFuncSetAttribute(mma_gemm_k<3,0,2>, cudaFuncAttributeMaxDynamicSharedMemorySize, SMEM_DYN);
        cudaFuncSetAttribute(mma_gemm_k<0,1,0>, cudaFuncAttributeMaxDynamicSharedMemorySize, SMEM_DYN);
    }

    float *h, *rowsum, *colsum;
    cudaGetSymbolAddress((void**)&h, g_h);
    cudaGetSymbolAddress((void**)&rowsum, g_rowsum);
    cudaGetSymbolAddress((void**)&colsum, g_colsum);

    fp16 *e16,*x16,*phi16,*W116,*W216,*dspT,*xin_h,*xin_l,*x2_h,*x2_l,*y16,*cmb;
    cudaGetSymbolAddress((void**)&e16, g_e16);
    cudaGetSymbolAddress((void**)&x16, g_x16);
    cudaGetSymbolAddress((void**)&phi16, g_phi16);
    cudaGetSymbolAddress((void**)&W116, g_W116);
    cudaGetSymbolAddress((void**)&W216, g_W216);
    cudaGetSymbolAddress((void**)&dspT, g_dspT);
    cudaGetSymbolAddress((void**)&xin_h, g_xin_h); cudaGetSymbolAddress((void**)&xin_l, g_xin_l);
    cudaGetSymbolAddress((void**)&x2_h, g_x2_h);   cudaGetSymbolAddress((void**)&x2_l, g_x2_l);
    cudaGetSymbolAddress((void**)&y16, g_y16);
    cudaGetSymbolAddress((void**)&cmb, g_cmb);

    const size_t EXP = (size_t)Eq * Sq * Dq;

    // fork side stream: W conversion (needed first by K4)
    cudaEventRecord(eFork, 0);
    cudaStreamWaitEvent(s_side, eFork, 0);
    convert_W_k<<<(int)((2 * N4_W + 255) / 256), 256, 0, s_side>>>(W1, W2, W116, W216);
    cudaEventRecord(eW, s_side);

    // main: zero denominators, convert x/phi, K1 (exp epilogue)
    cudaMemsetAsync(rowsum, 0, (size_t)Bq * Nq * sizeof(float), 0);
    cudaMemsetAsync(colsum, 0, (size_t)Bq * ESq * sizeof(float), 0);
    convert_xphi_k<<<(int)((N4_X + N4_PHI + 255) / 256), 256>>>(x, phi, x16, phi16);

    mma_gemm_k<4,0,0><<<dim3(ESq/BN, Nq/BM, Bq), 256, SMEM_DYN>>>(
        x16, phi16, nullptr, nullptr, nullptr, nullptr, e16, nullptr,
        rowsum, colsum,
        Dq, Dq, ESq, ESq,
        (size_t)Nq*Dq, 0, (size_t)Nq*ESq, 1, 0,
        (size_t)64*Dq, (size_t)64*ESq);

    // fused dispatch+combine (token-partitioned: 2048 blocks)
    softmax_both_k<<<dim3(ESq/32, Nq/256, Bq), 256>>>(e16, colsum, rowsum, dspT, cmb);

    // K3: xin[b] = dsp[b]^T @ x[b]
    mma_gemm_k<0,0,1><<<dim3(Dq/BN, ESq/BM, Bq), 256, SMEM_DYN>>>(
        dspT, x16, nullptr, nullptr, nullptr, nullptr, xin_h, xin_l,
        nullptr, nullptr,
        Nq, Nq, Dq, Dq,
        (size_t)ESq*Nq, (size_t)Nq*Dq, (size_t)ESq*Dq, Bq, 0,
        (size_t)64*Nq, (size_t)64*Dq);

    cudaStreamWaitEvent(0, eW, 0);

    // K4
    mma_gemm_k<1,1,0><<<dim3(Dq/BN, (Bq*Sq)/BM, Eq), 256, SMEM_DYN>>>(
        xin_h, W116, b1, nullptr, nullptr, h, nullptr, nullptr,
        nullptr, nullptr,
        Dq, Dq, Dq, Dq,
        (size_t)Sq*Dq, (size_t)Dq*Dq, (size_t)Sq*Dq, Eq, (size_t)Dq,
        EXP, EXP);

    ln_relu_k<<<Bq*Eq*Sq, 256>>>(h, xin_h, xin_l, g1, be1, x2_h, x2_l);

    // K6 -> fp16 y
    mma_gemm_k<3,0,2><<<dim3(Dq/BN, (Bq*Sq)/BM, Eq), 256, SMEM_DYN>>>(
        x2_h, W216, b2, x2_h, x2_l, nullptr, y16, nullptr,
        nullptr, nullptr,
        Dq, Dq, Dq, Dq,
        (size_t)Sq*Dq, (size_t)Dq*Dq, (size_t)Sq*Dq, Eq, (size_t)Dq,
        EXP, EXP);

    // K8
    mma_gemm_k<0,1,0><<<dim3(Dq/BN, Nq/BM, Bq), 256, SMEM_DYN>>>(
        cmb, y16, nullptr, nullptr, nullptr, out, nullptr, nullptr,
        nullptr, nullptr,
        ESq, ESq, Dq, Dq,
        (size_t)Nq*ESq, EXP, (size_t)Nq*Dq, Bq, 0,
        (size_t)64*ESq, (size_t)64*Dq);
}

// round 16
// speedup vs baseline: 1.0932x; 1.0036x over previous
#include <cuda_runtime.h>
#include <cuda_fp16.h>
#include <math.h>
#include <stdint.h>

typedef __half fp16;

#define Bq   8
#define Nq   2048
#define Dq   1024
#define Eq   16
#define Sq   64
#define ESq  1024
#define EPSq 1e-5f

// ---------------- scratch ----------------
__device__ __align__(16) float g_h  [(size_t)Bq * Eq * Sq * Dq];
__device__ __align__(16) float g_rowsum[(size_t)Bq * Nq];
__device__ __align__(16) float g_colsum[(size_t)Bq * ESq];

__device__ __align__(16) fp16 g_e16  [(size_t)Bq * Nq * ESq];   // exp(w) fp16 [N,ES]
__device__ __align__(16) fp16 g_eT   [(size_t)Bq * ESq * Nq];   // transposed  [ES,N]
__device__ __align__(16) fp16 g_x16  [(size_t)Bq * Nq * Dq];
__device__ __align__(16) fp16 g_phi16[(size_t)Dq * ESq];
__device__ __align__(16) fp16 g_W116 [(size_t)Eq * Dq * Dq];
__device__ __align__(16) fp16 g_W216 [(size_t)Eq * Dq * Dq];
__device__ __align__(16) fp16 g_xin_h[(size_t)Bq * Eq * Sq * Dq], g_xin_l[(size_t)Bq * Eq * Sq * Dq];
__device__ __align__(16) fp16 g_x2_h [(size_t)Bq * Eq * Sq * Dq], g_x2_l [(size_t)Bq * Eq * Sq * Dq];
__device__ __align__(16) fp16 g_y16  [(size_t)Bq * Eq * Sq * Dq];

// ===== mma.sync GEMM (R9 config): 256 thr, 2 CTA/SM, warp tile 64x32 =====
#define BM 128
#define BN 128
#define BK 64
#define NSTG 3
#define PA 144
#define PB 272
#define A_BYTES (128 * PA)
#define B_BYTES (64 * PB)
#define OFF_A 0
#define OFF_B A_BYTES
#define STAGE (A_BYTES + B_BYTES)
#define SMEM_DYN (NSTG * STAGE)       // 107520

__device__ __forceinline__ uint32_t s2u(const void* p) {
    uint32_t a;
    asm("{ .reg .u64 t; cvta.to.shared.u64 t, %1; cvt.u32.u64 %0, t; }" : "=r"(a) : "l"(p));
    return a;
}
__device__ __forceinline__ void cpa16(uint32_t dst, const void* src) {
    asm volatile("cp.async.cg.shared.global [%0], [%1], 16;" :: "r"(dst), "l"(src));
}
__device__ __forceinline__ void ldm_x4(uint32_t* r, uint32_t a) {
    asm volatile("ldmatrix.sync.aligned.m8n8.x4.shared.b16 {%0,%1,%2,%3}, [%4];"
                 : "=r"(r[0]), "=r"(r[1]), "=r"(r[2]), "=r"(r[3]) : "r"(a));
}
__device__ __forceinline__ void ldm_x4t(uint32_t* r, uint32_t a) {
    asm volatile("ldmatrix.sync.aligned.m8n8.x4.trans.shared.b16 {%0,%1,%2,%3}, [%4];"
                 : "=r"(r[0]), "=r"(r[1]), "=r"(r[2]), "=r"(r[3]) : "r"(a));
}
__device__ __forceinline__ void mma16816(float* c, const uint32_t* a, const uint32_t* b) {
    asm volatile(
        "mma.sync.aligned.m16n8k16.row.col.f32.f16.f16.f32 "
        "{%0,%1,%2,%3}, {%4,%5,%6,%7}, {%8,%9}, {%0,%1,%2,%3};"
        : "+f"(c[0]), "+f"(c[1]), "+f"(c[2]), "+f"(c[3])
        : "r"(a[0]), "r"(a[1]), "r"(a[2]), "r"(a[3]), "r"(b[0]), "r"(b[1]));
}

// EPI: 0 none, 1 +bias, 3 +bias+(resh+resl),
//      4 exp-stats (write fp16 exp to Chb, atomics into rowsumb/colsumb),
//      5 row-scale: v *= 1/scale[z*sScale + row]  (scale passed via rowsumb)
// WC: write fp32 C.  SPLIT: 0 none, 1 fp16 hi+lo, 2 fp16 hi only.
template<int EPI, int WC, int SPLIT>
__global__ void __launch_bounds__(256, 2)
mma_gemm_k(const fp16* __restrict__ Ab, const fp16* __restrict__ Bb,
           const float* __restrict__ biasb,
           const fp16* __restrict__ reshb, const fp16* __restrict__ reslb,
           float* __restrict__ Cb, fp16* __restrict__ Chb, fp16* __restrict__ Clb,
           float* __restrict__ rowsumb, float* __restrict__ colsumb, size_t sScale,
           int K, int lda, int ldb, int ldc,
           size_t sA, size_t sB, size_t sC, int bMod, size_t sBias,
           size_t aRowBlk, size_t cRowBlk)
{
    extern __shared__ char sm[];
    const uint32_t sb = s2u(sm);
    const int tid = threadIdx.x, wid = tid >> 5, lane = tid & 31;
    const int z = blockIdx.z;

    const fp16* A = Ab + (size_t)z * sA;
    const fp16* B = Bb + (size_t)(z % bMod) * sB;

    const int m0 = blockIdx.y * BM;
    const int n0 = blockIdx.x * BN;

    size_t aoff[4]; uint32_t adst[4];
#pragma unroll
    for (int i = 0; i < 4; i++) {
        const int idx = tid + i * 256;
        const int row = idx >> 3, kc = idx & 7;
        const int m = m0 + row;
        aoff[i] = ((size_t)(m >> 6)) * aRowBlk + (size_t)(m & 63) * lda + kc * 8;
        adst[i] = (uint32_t)(row * PA + kc * 16);
    }
    size_t boff[4]; uint32_t bdst[4];
#pragma unroll
    for (int i = 0; i < 4; i++) {
        const int idx = tid + i * 256;
        const int row = idx >> 4, nc = idx & 15;
        boff[i] = (size_t)row * ldb + n0 + nc * 8;
        bdst[i] = (uint32_t)(row * PB + nc * 16);
    }

    auto load_stage = [&](int t) {
        const uint32_t stg = sb + (t % NSTG) * STAGE;
        const size_t ke = (size_t)t * BK;
#pragma unroll
        for (int i = 0; i < 4; i++) cpa16(stg + OFF_A + adst[i], A + aoff[i] + ke);
        const size_t kb = ke * ldb;
#pragma unroll
        for (int i = 0; i < 4; i++) cpa16(stg + OFF_B + bdst[i], B + boff[i] + kb);
        asm volatile("cp.async.commit_group;" ::: "memory");
    };

    const int wm = (wid >> 2) * 64;
    const int wn = (wid & 3) * 32;

    float acc[4][4][4];
#pragma unroll
    for (int mi = 0; mi < 4; mi++)
#pragma unroll
        for (int ni = 0; ni < 4; ni++)
#pragma unroll
            for (int q = 0; q < 4; q++) acc[mi][ni][q] = 0.f;

    const int nt = K / BK;
    load_stage(0);
    if (nt > 1) load_stage(1);

    for (int t = 0; t < nt; t++) {
        if (t + 1 < nt) asm volatile("cp.async.wait_group 1;" ::: "memory");
        else            asm volatile("cp.async.wait_group 0;" ::: "memory");
        __syncthreads();
        if (t + 2 < nt) load_stage(t + 2);

        const uint32_t stg = sb + (t % NSTG) * STAGE;
#pragma unroll
        for (int ks = 0; ks < 4; ks++) {
            const int kb = ks * 16;
            uint32_t ah[4][4], bh[2][4];
#pragma unroll
            for (int mi = 0; mi < 4; mi++) {
                const uint32_t ao =
                    (uint32_t)((wm + mi * 16 + (lane & 15)) * PA + (kb + (lane >> 4) * 8) * 2);
                ldm_x4(ah[mi], stg + OFF_A + ao);
            }
#pragma unroll
            for (int nj = 0; nj < 2; nj++) {
                const uint32_t bo =
                    (uint32_t)((kb + (lane & 15)) * PB + (wn + nj * 16 + (lane >> 4) * 8) * 2);
                ldm_x4t(bh[nj], stg + OFF_B + bo);
            }
#pragma unroll
            for (int mi = 0; mi < 4; mi++)
#pragma unroll
                for (int ni = 0; ni < 4; ni++)
                    mma16816(acc[mi][ni], ah[mi], &bh[ni >> 1][(ni & 1) * 2]);
        }
    }

    // ---------------- epilogue ----------------
    float*       C  = WC ? (Cb + (size_t)z * sC) : nullptr;
    fp16*        Ch = (SPLIT || EPI == 4) ? (Chb + (size_t)z * sC) : nullptr;
    fp16*        Cl = (SPLIT == 1) ? (Clb + (size_t)z * sC) : nullptr;
    const float* bias = (EPI == 1 || EPI == 3) ? (biasb + (size_t)(z % bMod) * sBias) : nullptr;
    const fp16*  resh = (EPI == 3) ? (reshb + (size_t)z * sC) : nullptr;
    const fp16*  resl = (EPI == 3) ? (reslb + (size_t)z * sC) : nullptr;
    const float* scl  = (EPI == 5) ? (rowsumb + (size_t)z * sScale) : nullptr;

    float rsumA[4], rsumB[4], csum[4][2];
    if (EPI == 4) {
#pragma unroll
        for (int mi = 0; mi < 4; mi++) { rsumA[mi] = 0.f; rsumB[mi] = 0.f; }
#pragma unroll
        for (int ni = 0; ni < 4; ni++) { csum[ni][0] = 0.f; csum[ni][1] = 0.f; }
    }

#pragma unroll
    for (int mi = 0; mi < 4; mi++) {
        const int mA = m0 + wm + mi * 16 + (lane >> 2);
        const int mB = mA + 8;
        const size_t coA = ((size_t)(mA >> 6)) * cRowBlk + (size_t)(mA & 63) * ldc;
        const size_t coB = ((size_t)(mB >> 6)) * cRowBlk + (size_t)(mB & 63) * ldc;
        float invA = 1.f, invB = 1.f;
        if (EPI == 5) { invA = 1.f / scl[mA]; invB = 1.f / scl[mB]; }
#pragma unroll
        for (int ni = 0; ni < 4; ni++) {
            const int col = n0 + wn + ni * 8 + (lane & 3) * 2;
            float2 v0 = make_float2(acc[mi][ni][0], acc[mi][ni][1]);
            float2 v1 = make_float2(acc[mi][ni][2], acc[mi][ni][3]);
            if (EPI == 1 || EPI == 3) {
                const float2 bb = *reinterpret_cast<const float2*>(&bias[col]);
                v0.x += bb.x; v0.y += bb.y; v1.x += bb.x; v1.y += bb.y;
            }
            if (EPI == 3) {
                const __half2 hA = *reinterpret_cast<const __half2*>(&resh[coA + col]);
                const __half2 lA = *reinterpret_cast<const __half2*>(&resl[coA + col]);
                const __half2 hB = *reinterpret_cast<const __half2*>(&resh[coB + col]);
                const __half2 lB = *reinterpret_cast<const __half2*>(&resl[coB + col]);
                v0.x += __half2float(hA.x) + __half2float(lA.x);
                v0.y += __half2float(hA.y) + __half2float(lA.y);
                v1.x += __half2float(hB.x) + __half2float(lB.x);
                v1.y += __half2float(hB.y) + __half2float(lB.y);
            }
            if (EPI == 5) { v0.x *= invA; v0.y *= invA; v1.x *= invB; v1.y *= invB; }
            if (EPI == 4) {
                const float e0 = __expf(v0.x), e1 = __expf(v0.y);
                const float e2 = __expf(v1.x), e3 = __expf(v1.y);
                rsumA[mi] += e0 + e1;
                rsumB[mi] += e2 + e3;
                csum[ni][0] += e0 + e2;
                csum[ni][1] += e1 + e3;
                *reinterpret_cast<__half2*>(&Ch[coA + col]) =
                    __halves2half2(__float2half_rn(e0), __float2half_rn(e1));
                *reinterpret_cast<__half2*>(&Ch[coB + col]) =
                    __halves2half2(__float2half_rn(e2), __float2half_rn(e3));
            }
            if (WC) {
                *reinterpret_cast<float2*>(&C[coA + col]) = v0;
                *reinterpret_cast<float2*>(&C[coB + col]) = v1;
            }
            if (SPLIT) {
                fp16 h0 = __float2half_rn(v0.x), h1 = __float2half_rn(v0.y);
                fp16 h2 = __float2half_rn(v1.x), h3 = __float2half_rn(v1.y);
                *reinterpret_cast<__half2*>(&Ch[coA + col]) = __halves2half2(h0, h1);
                *reinterpret_cast<__half2*>(&Ch[coB + col]) = __halves2half2(h2, h3);
                if (SPLIT == 1) {
                    *reinterpret_cast<__half2*>(&Cl[coA + col]) = __halves2half2(
                        __float2half_rn(v0.x - __half2float(h0)),
                        __float2half_rn(v0.y - __half2float(h1)));
                    *reinterpret_cast<__half2*>(&Cl[coB + col]) = __halves2half2(
                        __float2half_rn(v1.x - __half2float(h2)),
                        __float2half_rn(v1.y - __half2float(h3)));
                }
            }
        }
    }

    if (EPI == 4) {
        float* rowsum = rowsumb + (size_t)z * Nq;
        float* colsum = colsumb + (size_t)z * ESq;
#pragma unroll
        for (int mi = 0; mi < 4; mi++) {
            float ra = rsumA[mi], rb = rsumB[mi];
            ra += __shfl_xor_sync(0xffffffffu, ra, 1);
            ra += __shfl_xor_sync(0xffffffffu, ra, 2);
            rb += __shfl_xor_sync(0xffffffffu, rb, 1);
            rb += __shfl_xor_sync(0xffffffffu, rb, 2);
            if ((lane & 3) == 0) {
                const int mA = m0 + wm + mi * 16 + (lane >> 2);
                atomicAdd(&rowsum[mA], ra);
                atomicAdd(&rowsum[mA + 8], rb);
            }
        }
#pragma unroll
        for (int ni = 0; ni < 4; ni++) {
            float c0 = csum[ni][0], c1 = csum[ni][1];
            c0 += __shfl_xor_sync(0xffffffffu, c0, 4);
            c0 += __shfl_xor_sync(0xffffffffu, c0, 8);
            c0 += __shfl_xor_sync(0xffffffffu, c0, 16);
            c1 += __shfl_xor_sync(0xffffffffu, c1, 4);
            c1 += __shfl_xor_sync(0xffffffffu, c1, 8);
            c1 += __shfl_xor_sync(0xffffffffu, c1, 16);
            if ((lane >> 2) == 0) {
                const int col = n0 + wn + ni * 8 + (lane & 3) * 2;
                atomicAdd(&colsum[col], c0);
                atomicAdd(&colsum[col + 1], c1);
            }
        }
    }
}

// ====== conversions ======
#define N4_X   ((size_t)Bq * Nq * Dq / 4)
#define N4_PHI ((size_t)Dq * ESq / 4)
#define N4_W   ((size_t)Eq * Dq * Dq / 4)

__global__ void convert_xphi_k(const float* __restrict__ x, const float* __restrict__ phi,
                               fp16* __restrict__ ox, fp16* __restrict__ ophi)
{
    size_t i = (size_t)blockIdx.x * blockDim.x + threadIdx.x;
    if (i >= N4_X + N4_PHI) return;
    const float* in; fp16* o;
    if (i < N4_X) { in = x; o = ox; }
    else          { i -= N4_X; in = phi; o = ophi; }
    const float4 v = reinterpret_cast<const float4*>(in)[i];
    reinterpret_cast<__half2*>(o)[2 * i] =
        __halves2half2(__float2half_rn(v.x), __float2half_rn(v.y));
    reinterpret_cast<__half2*>(o)[2 * i + 1] =
        __halves2half2(__float2half_rn(v.z), __float2half_rn(v.w));
}

__global__ void convert_W_k(const float* __restrict__ W1, const float* __restrict__ W2,
                            fp16* __restrict__ oW1, fp16* __restrict__ oW2)
{
    size_t i = (size_t)blockIdx.x * blockDim.x + threadIdx.x;
    if (i >= 2 * N4_W) return;
    const float* in; fp16* o;
    if (i < N4_W) { in = W1; o = oW1; }
    else          { i -= N4_W; in = W2; o = oW2; }
    const float4 v = reinterpret_cast<const float4*>(in)[i];
    reinterpret_cast<__half2*>(o)[2 * i] =
        __halves2half2(__float2half_rn(v.x), __float2half_rn(v.y));
    reinterpret_cast<__half2*>(o)[2 * i + 1] =
        __halves2half2(__float2half_rn(v.z), __float2half_rn(v.w));
}

// ====== pure fp16 transpose: e16 [N,ES] -> eT [ES,N], per batch ======
// grid: (ESq/32, Nq/256, Bq), 256 thr
__global__ void transpose_k(const fp16* __restrict__ e16, fp16* __restrict__ eT)
{
    const int b = blockIdx.z, lane = threadIdx.x & 31, grp = threadIdx.x >> 5;
    const int col0 = blockIdx.x * 32;
    const int nbase = blockIdx.y * 256;
    const fp16* p = e16 + (size_t)b * Nq * ESq + col0;

    __shared__ fp16 t[32][40];

    const size_t obase = (size_t)b * ESq * Nq;
    for (int nc = 0; nc < 256; nc += 32) {
        const int n0 = nbase + nc;
#pragma unroll
        for (int i = 0; i < 4; i++) {
            const int r = grp * 4 + i;
            t[r][lane] = p[(size_t)(n0 + r) * ESq + lane];
        }
        __syncthreads();
#pragma unroll
        for (int i = 0; i < 4; i++) {
            const int cc = grp * 4 + i;
            eT[obase + (size_t)(col0 + cc) * Nq + n0 + lane] = t[lane][cc];
        }
        __syncthreads();
    }
}

// ===== LN + relu + residual =====
__global__ void ln_relu_k(const float* __restrict__ h,
                          const fp16* __restrict__ xh, const fp16* __restrict__ xl,
                          const float* __restrict__ g, const float* __restrict__ be,
                          fp16* __restrict__ oh, fp16* __restrict__ ol)
{
    const int r = blockIdx.x;
    const int e = (r / Sq) % Eq;
    const float* hr = h + (size_t)r * Dq;
    const int tid = threadIdx.x;
    __shared__ float rs[256], rs2[256];

    float v[4];
    float s = 0.f, s2 = 0.f;
#pragma unroll
    for (int j = 0; j < 4; j++) {
        v[j] = hr[tid + 256 * j];
        s += v[j]; s2 += v[j] * v[j];
    }
    rs[tid] = s; rs2[tid] = s2;
    __syncthreads();
    for (int off = 128; off > 0; off >>= 1) {
        if (tid < off) { rs[tid] += rs[tid + off]; rs2[tid] += rs2[tid + off]; }
        __syncthreads();
    }
    const float mean = rs[0] * (1.f / Dq);
    const float var  = rs2[0] * (1.f / Dq) - mean * mean;
    const float rstd = rsqrtf(var + EPSq);

#pragma unroll
    for (int j = 0; j < 4; j++) {
        const int d = tid + 256 * j;
        const size_t o = (size_t)r * Dq + d;
        const float xr = __half2float(xh[o]) + __half2float(xl[o]);
        const float ln = (v[j] - mean) * rstd * g[(size_t)e * Dq + d] + be[(size_t)e * Dq + d];
        const float val = xr + fmaxf(ln, 0.f);
        fp16 hh = __float2half_rn(val);
        oh[o] = hh;
        ol[o] = __float2half_rn(val - __half2float(hh));
    }
}

// ================= launch =================
extern "C" void kernel_launch(void* const* d_in, const int* in_sizes, int n_in,
                              void* d_out, int out_size)
{
    const float* x   = (const float*)d_in[0];
    const float* phi = (const float*)d_in[1];
    const float* W1  = (const float*)d_in[2];
    const float* b1  = (const float*)d_in[3];
    const float* g1  = (const float*)d_in[4];
    const float* be1 = (const float*)d_in[5];
    const float* W2  = (const float*)d_in[6];
    const float* b2  = (const float*)d_in[7];
    float* out = (float*)d_out;

    static cudaStream_t s_side = nullptr;
    static cudaEvent_t eFork = nullptr, eW = nullptr;
    if (s_side == nullptr) {
        cudaStreamCreateWithFlags(&s_side, cudaStreamNonBlocking);
        cudaEventCreateWithFlags(&eFork, cudaEventDisableTiming);
        cudaEventCreateWithFlags(&eW,    cudaEventDisableTiming);
        cudaFuncSetAttribute(mma_gemm_k<4,0,0>, cudaFuncAttributeMaxDynamicSharedMemorySize, SMEM_DYN);
        cudaFuncSetAttribute(mma_gemm_k<5,0,1>, cudaFuncAttributeMaxDynamicSharedMemorySize, SMEM_DYN);
        cudaFuncSetAttribute(mma_gemm_k<1,1,0>, cudaFuncAttributeMaxDynamicSharedMemorySize, SMEM_DYN);
        cudaFuncSetAttribute(mma_gemm_k<3,0,2>, cudaFuncAttributeMaxDynamicSharedMemorySize, SMEM_DYN);
        cudaFuncSetAttribute(mma_gemm_k<5,1,0>, cudaFuncAttributeMaxDynamicSharedMemorySize, SMEM_DYN);
    }

    float *h, *rowsum, *colsum;
    cudaGetSymbolAddress((void**)&h, g_h);
    cudaGetSymbolAddress((void**)&rowsum, g_rowsum);
    cudaGetSymbolAddress((void**)&colsum, g_colsum);

    fp16 *e16,*eT,*x16,*phi16,*W116,*W216,*xin_h,*xin_l,*x2_h,*x2_l,*y16;
    cudaGetSymbolAddress((void**)&e16, g_e16);
    cudaGetSymbolAddress((void**)&eT,  g_eT);
    cudaGetSymbolAddress((void**)&x16, g_x16);
    cudaGetSymbolAddress((void**)&phi16, g_phi16);
    cudaGetSymbolAddress((void**)&W116, g_W116);
    cudaGetSymbolAddress((void**)&W216, g_W216);
    cudaGetSymbolAddress((void**)&xin_h, g_xin_h); cudaGetSymbolAddress((void**)&xin_l, g_xin_l);
    cudaGetSymbolAddress((void**)&x2_h, g_x2_h);   cudaGetSymbolAddress((void**)&x2_l, g_x2_l);
    cudaGetSymbolAddress((void**)&y16, g_y16);

    const size_t EXP = (size_t)Eq * Sq * Dq;

    // fork side stream: W conversion (needed first by K4)
    cudaEventRecord(eFork, 0);
    cudaStreamWaitEvent(s_side, eFork, 0);
    convert_W_k<<<(int)((2 * N4_W + 255) / 256), 256, 0, s_side>>>(W1, W2, W116, W216);
    cudaEventRecord(eW, s_side);

    // main: zero denominators, convert x/phi, K1 (exp epilogue)
    cudaMemsetAsync(rowsum, 0, (size_t)Bq * Nq * sizeof(float), 0);
    cudaMemsetAsync(colsum, 0, (size_t)Bq * ESq * sizeof(float), 0);
    convert_xphi_k<<<(int)((N4_X + N4_PHI + 255) / 256), 256>>>(x, phi, x16, phi16);

    mma_gemm_k<4,0,0><<<dim3(ESq/BN, Nq/BM, Bq), 256, SMEM_DYN>>>(
        x16, phi16, nullptr, nullptr, nullptr, nullptr, e16, nullptr,
        rowsum, colsum, 0,
        Dq, Dq, ESq, ESq,
        (size_t)Nq*Dq, 0, (size_t)Nq*ESq, 1, 0,
        (size_t)64*Dq, (size_t)64*ESq);

    // transpose e16 -> eT (scaling folded into K3/K8 epilogues)
    transpose_k<<<dim3(ESq/32, Nq/256, Bq), 256>>>(e16, eT);

    // K3: xin[b] = (eT @ x) / colsum[row]   M=ES N=D K=N
    mma_gemm_k<5,0,1><<<dim3(Dq/BN, ESq/BM, Bq), 256, SMEM_DYN>>>(
        eT, x16, nullptr, nullptr, nullptr, nullptr, xin_h, xin_l,
        colsum, nullptr, (size_t)ESq,
        Nq, Nq, Dq, Dq,
        (size_t)ESq*Nq, (size_t)Nq*Dq, (size_t)ESq*Dq, Bq, 0,
        (size_t)64*Nq, (size_t)64*Dq);

    cudaStreamWaitEvent(0, eW, 0);

    // K4
    mma_gemm_k<1,1,0><<<dim3(Dq/BN, (Bq*Sq)/BM, Eq), 256, SMEM_DYN>>>(
        xin_h, W116, b1, nullptr, nullptr, h, nullptr, nullptr,
        nullptr, nullptr, 0,
        Dq, Dq, Dq, Dq,
        (size_t)Sq*Dq, (size_t)Dq*Dq, (size_t)Sq*Dq, Eq, (size_t)Dq,
        EXP, EXP);

    ln_relu_k<<<Bq*Eq*Sq, 256>>>(h, xin_h, xin_l, g1, be1, x2_h, x2_l);

    // K6 -> fp16 y
    mma_gemm_k<3,0,2><<<dim3(Dq/BN, (Bq*Sq)/BM, Eq), 256, SMEM_DYN>>>(
        x2_h, W216, b2, x2_h, x2_l, nullptr, y16, nullptr,
        nullptr, nullptr, 0,
        Dq, Dq, Dq, Dq,
        (size_t)Sq*Dq, (size_t)Dq*Dq, (size_t)Sq*Dq, Eq, (size_t)Dq,
        EXP, EXP);

    // K8: out[b] = (e16 @ y16) / rowsum[row]   M=N N=D K=ES
    mma_gemm_k<5,1,0><<<dim3(Dq/BN, Nq/BM, Bq), 256, SMEM_DYN>>>(
        e16, y16, nullptr, nullptr, nullptr, out, nullptr, nullptr,
        rowsum, nullptr, (size_t)Nq,
        ESq, ESq, Dq, Dq,
        (size_t)Nq*ESq, EXP, (size_t)Nq*Dq, Bq, 0,
        (size_t)64*ESq, (size_t)64*Dq);
}

// round 17
// speedup vs baseline: 1.1008x; 1.0069x over previous
#include <cuda_runtime.h>
#include <cuda_fp16.h>
#include <math.h>
#include <stdint.h>

typedef __half fp16;

#define Bq   8
#define Nq   2048
#define Dq   1024
#define Eq   16
#define Sq   64
#define ESq  1024
#define EPSq 1e-5f

// ---------------- scratch ----------------
__device__ __align__(16) float g_h  [(size_t)Bq * Eq * Sq * Dq];
__device__ __align__(16) float g_rowsum[(size_t)Bq * Nq];
__device__ __align__(16) float g_colsum[(size_t)Bq * ESq];

__device__ __align__(16) fp16 g_e16  [(size_t)Bq * Nq * ESq];
__device__ __align__(16) fp16 g_eT   [(size_t)Bq * ESq * Nq];
__device__ __align__(16) fp16 g_x16  [(size_t)Bq * Nq * Dq];
__device__ __align__(16) fp16 g_phi16[(size_t)Dq * ESq];
__device__ __align__(16) fp16 g_W116 [(size_t)Eq * Dq * Dq];
__device__ __align__(16) fp16 g_W216 [(size_t)Eq * Dq * Dq];
__device__ __align__(16) fp16 g_xin_h[(size_t)Bq * Eq * Sq * Dq], g_xin_l[(size_t)Bq * Eq * Sq * Dq];
__device__ __align__(16) fp16 g_x2_h [(size_t)Bq * Eq * Sq * Dq], g_x2_l [(size_t)Bq * Eq * Sq * Dq];
__device__ __align__(16) fp16 g_y16  [(size_t)Bq * Eq * Sq * Dq];

// ===== mma.sync GEMM (R9 config): 256 thr, 2 CTA/SM, warp tile 64x32 =====
#define BM 128
#define BN 128
#define BK 64
#define NSTG 3
#define PA 144
#define PB 272
#define A_BYTES (128 * PA)
#define B_BYTES (64 * PB)
#define OFF_A 0
#define OFF_B A_BYTES
#define STAGE (A_BYTES + B_BYTES)
#define SMEM_DYN (NSTG * STAGE)       // 107520

__device__ __forceinline__ uint32_t s2u(const void* p) {
    uint32_t a;
    asm("{ .reg .u64 t; cvta.to.shared.u64 t, %1; cvt.u32.u64 %0, t; }" : "=r"(a) : "l"(p));
    return a;
}
__device__ __forceinline__ void cpa16(uint32_t dst, const void* src) {
    asm volatile("cp.async.cg.shared.global [%0], [%1], 16;" :: "r"(dst), "l"(src));
}
__device__ __forceinline__ void ldm_x4(uint32_t* r, uint32_t a) {
    asm volatile("ldmatrix.sync.aligned.m8n8.x4.shared.b16 {%0,%1,%2,%3}, [%4];"
                 : "=r"(r[0]), "=r"(r[1]), "=r"(r[2]), "=r"(r[3]) : "r"(a));
}
__device__ __forceinline__ void ldm_x4t(uint32_t* r, uint32_t a) {
    asm volatile("ldmatrix.sync.aligned.m8n8.x4.trans.shared.b16 {%0,%1,%2,%3}, [%4];"
                 : "=r"(r[0]), "=r"(r[1]), "=r"(r[2]), "=r"(r[3]) : "r"(a));
}
__device__ __forceinline__ void mma16816(float* c, const uint32_t* a, const uint32_t* b) {
    asm volatile(
        "mma.sync.aligned.m16n8k16.row.col.f32.f16.f16.f32 "
        "{%0,%1,%2,%3}, {%4,%5,%6,%7}, {%8,%9}, {%0,%1,%2,%3};"
        : "+f"(c[0]), "+f"(c[1]), "+f"(c[2]), "+f"(c[3])
        : "r"(a[0]), "r"(a[1]), "r"(a[2]), "r"(a[3]), "r"(b[0]), "r"(b[1]));
}

// EPI: 0 none, 1 +bias, 3 +bias+(resh+resl),
//      4 exp-stats (write fp16 exp to Chb, atomics into rowsumb/colsumb),
//      5 row-scale: v *= 1/scale[z*sScale + row]
// WC: write fp32 C.  SPLIT: 0 none, 1 fp16 hi+lo, 2 fp16 hi only.
template<int EPI, int WC, int SPLIT>
__global__ void __launch_bounds__(256, 2)
mma_gemm_k(const fp16* __restrict__ Ab, const fp16* __restrict__ Bb,
           const float* __restrict__ biasb,
           const fp16* __restrict__ reshb, const fp16* __restrict__ reslb,
           float* __restrict__ Cb, fp16* __restrict__ Chb, fp16* __restrict__ Clb,
           float* __restrict__ rowsumb, float* __restrict__ colsumb, size_t sScale,
           int K, int lda, int ldb, int ldc,
           size_t sA, size_t sB, size_t sC, int bMod, size_t sBias,
           size_t aRowBlk, size_t cRowBlk)
{
    extern __shared__ char sm[];
    const uint32_t sb = s2u(sm);
    const int tid = threadIdx.x, wid = tid >> 5, lane = tid & 31;
    const int z = blockIdx.z;

    const fp16* A = Ab + (size_t)z * sA;
    const fp16* B = Bb + (size_t)(z % bMod) * sB;

    const int m0 = blockIdx.y * BM;
    const int n0 = blockIdx.x * BN;

    size_t aoff[4]; uint32_t adst[4];
#pragma unroll
    for (int i = 0; i < 4; i++) {
        const int idx = tid + i * 256;
        const int row = idx >> 3, kc = idx & 7;
        const int m = m0 + row;
        aoff[i] = ((size_t)(m >> 6)) * aRowBlk + (size_t)(m & 63) * lda + kc * 8;
        adst[i] = (uint32_t)(row * PA + kc * 16);
    }
    size_t boff[4]; uint32_t bdst[4];
#pragma unroll
    for (int i = 0; i < 4; i++) {
        const int idx = tid + i * 256;
        const int row = idx >> 4, nc = idx & 15;
        boff[i] = (size_t)row * ldb + n0 + nc * 8;
        bdst[i] = (uint32_t)(row * PB + nc * 16);
    }

    auto load_stage = [&](int t) {
        const uint32_t stg = sb + (t % NSTG) * STAGE;
        const size_t ke = (size_t)t * BK;
#pragma unroll
        for (int i = 0; i < 4; i++) cpa16(stg + OFF_A + adst[i], A + aoff[i] + ke);
        const size_t kb = ke * ldb;
#pragma unroll
        for (int i = 0; i < 4; i++) cpa16(stg + OFF_B + bdst[i], B + boff[i] + kb);
        asm volatile("cp.async.commit_group;" ::: "memory");
    };

    const int wm = (wid >> 2) * 64;
    const int wn = (wid & 3) * 32;

    float acc[4][4][4];
#pragma unroll
    for (int mi = 0; mi < 4; mi++)
#pragma unroll
        for (int ni = 0; ni < 4; ni++)
#pragma unroll
            for (int q = 0; q < 4; q++) acc[mi][ni][q] = 0.f;

    const int nt = K / BK;
    load_stage(0);
    if (nt > 1) load_stage(1);

    for (int t = 0; t < nt; t++) {
        if (t + 1 < nt) asm volatile("cp.async.wait_group 1;" ::: "memory");
        else            asm volatile("cp.async.wait_group 0;" ::: "memory");
        __syncthreads();
        if (t + 2 < nt) load_stage(t + 2);

        const uint32_t stg = sb + (t % NSTG) * STAGE;
#pragma unroll
        for (int ks = 0; ks < 4; ks++) {
            const int kb = ks * 16;
            uint32_t ah[4][4], bh[2][4];
#pragma unroll
            for (int mi = 0; mi < 4; mi++) {
                const uint32_t ao =
                    (uint32_t)((wm + mi * 16 + (lane & 15)) * PA + (kb + (lane >> 4) * 8) * 2);
                ldm_x4(ah[mi], stg + OFF_A + ao);
            }
#pragma unroll
            for (int nj = 0; nj < 2; nj++) {
                const uint32_t bo =
                    (uint32_t)((kb + (lane & 15)) * PB + (wn + nj * 16 + (lane >> 4) * 8) * 2);
                ldm_x4t(bh[nj], stg + OFF_B + bo);
            }
#pragma unroll
            for (int mi = 0; mi < 4; mi++)
#pragma unroll
                for (int ni = 0; ni < 4; ni++)
                    mma16816(acc[mi][ni], ah[mi], &bh[ni >> 1][(ni & 1) * 2]);
        }
    }

    // ---------------- epilogue ----------------
    float*       C  = WC ? (Cb + (size_t)z * sC) : nullptr;
    fp16*        Ch = (SPLIT || EPI == 4) ? (Chb + (size_t)z * sC) : nullptr;
    fp16*        Cl = (SPLIT == 1) ? (Clb + (size_t)z * sC) : nullptr;
    const float* bias = (EPI == 1 || EPI == 3) ? (biasb + (size_t)(z % bMod) * sBias) : nullptr;
    const fp16*  resh = (EPI == 3) ? (reshb + (size_t)z * sC) : nullptr;
    const fp16*  resl = (EPI == 3) ? (reslb + (size_t)z * sC) : nullptr;
    const float* scl  = (EPI == 5) ? (rowsumb + (size_t)z * sScale) : nullptr;

    float rsumA[4], rsumB[4], csum[4][2];
    if (EPI == 4) {
#pragma unroll
        for (int mi = 0; mi < 4; mi++) { rsumA[mi] = 0.f; rsumB[mi] = 0.f; }
#pragma unroll
        for (int ni = 0; ni < 4; ni++) { csum[ni][0] = 0.f; csum[ni][1] = 0.f; }
    }

#pragma unroll
    for (int mi = 0; mi < 4; mi++) {
        const int mA = m0 + wm + mi * 16 + (lane >> 2);
        const int mB = mA + 8;
        const size_t coA = ((size_t)(mA >> 6)) * cRowBlk + (size_t)(mA & 63) * ldc;
        const size_t coB = ((size_t)(mB >> 6)) * cRowBlk + (size_t)(mB & 63) * ldc;
        float invA = 1.f, invB = 1.f;
        if (EPI == 5) { invA = 1.f / scl[mA]; invB = 1.f / scl[mB]; }
#pragma unroll
        for (int ni = 0; ni < 4; ni++) {
            const int col = n0 + wn + ni * 8 + (lane & 3) * 2;
            float2 v0 = make_float2(acc[mi][ni][0], acc[mi][ni][1]);
            float2 v1 = make_float2(acc[mi][ni][2], acc[mi][ni][3]);
            if (EPI == 1 || EPI == 3) {
                const float2 bb = *reinterpret_cast<const float2*>(&bias[col]);
                v0.x += bb.x; v0.y += bb.y; v1.x += bb.x; v1.y += bb.y;
            }
            if (EPI == 3) {
                const __half2 hA = *reinterpret_cast<const __half2*>(&resh[coA + col]);
                const __half2 lA = *reinterpret_cast<const __half2*>(&resl[coA + col]);
                const __half2 hB = *reinterpret_cast<const __half2*>(&resh[coB + col]);
                const __half2 lB = *reinterpret_cast<const __half2*>(&resl[coB + col]);
                v0.x += __half2float(hA.x) + __half2float(lA.x);
                v0.y += __half2float(hA.y) + __half2float(lA.y);
                v1.x += __half2float(hB.x) + __half2float(lB.x);
                v1.y += __half2float(hB.y) + __half2float(lB.y);
            }
            if (EPI == 5) { v0.x *= invA; v0.y *= invA; v1.x *= invB; v1.y *= invB; }
            if (EPI == 4) {
                const float e0 = __expf(v0.x), e1 = __expf(v0.y);
                const float e2 = __expf(v1.x), e3 = __expf(v1.y);
                rsumA[mi] += e0 + e1;
                rsumB[mi] += e2 + e3;
                csum[ni][0] += e0 + e2;
                csum[ni][1] += e1 + e3;
                *reinterpret_cast<__half2*>(&Ch[coA + col]) =
                    __halves2half2(__float2half_rn(e0), __float2half_rn(e1));
                *reinterpret_cast<__half2*>(&Ch[coB + col]) =
                    __halves2half2(__float2half_rn(e2), __float2half_rn(e3));
            }
            if (WC) {
                *reinterpret_cast<float2*>(&C[coA + col]) = v0;
                *reinterpret_cast<float2*>(&C[coB + col]) = v1;
            }
            if (SPLIT) {
                fp16 h0 = __float2half_rn(v0.x), h1 = __float2half_rn(v0.y);
                fp16 h2 = __float2half_rn(v1.x), h3 = __float2half_rn(v1.y);
                *reinterpret_cast<__half2*>(&Ch[coA + col]) = __halves2half2(h0, h1);
                *reinterpret_cast<__half2*>(&Ch[coB + col]) = __halves2half2(h2, h3);
                if (SPLIT == 1) {
                    *reinterpret_cast<__half2*>(&Cl[coA + col]) = __halves2half2(
                        __float2half_rn(v0.x - __half2float(h0)),
                        __float2half_rn(v0.y - __half2float(h1)));
                    *reinterpret_cast<__half2*>(&Cl[coB + col]) = __halves2half2(
                        __float2half_rn(v1.x - __half2float(h2)),
                        __float2half_rn(v1.y - __half2float(h3)));
                }
            }
        }
    }

    if (EPI == 4) {
        float* rowsum = rowsumb + (size_t)z * Nq;
        float* colsum = colsumb + (size_t)z * ESq;
#pragma unroll
        for (int mi = 0; mi < 4; mi++) {
            float ra = rsumA[mi], rb = rsumB[mi];
            ra += __shfl_xor_sync(0xffffffffu, ra, 1);
            ra += __shfl_xor_sync(0xffffffffu, ra, 2);
            rb += __shfl_xor_sync(0xffffffffu, rb, 1);
            rb += __shfl_xor_sync(0xffffffffu, rb, 2);
            if ((lane & 3) == 0) {
                const int mA = m0 + wm + mi * 16 + (lane >> 2);
                atomicAdd(&rowsum[mA], ra);
                atomicAdd(&rowsum[mA + 8], rb);
            }
        }
#pragma unroll
        for (int ni = 0; ni < 4; ni++) {
            float c0 = csum[ni][0], c1 = csum[ni][1];
            c0 += __shfl_xor_sync(0xffffffffu, c0, 4);
            c0 += __shfl_xor_sync(0xffffffffu, c0, 8);
            c0 += __shfl_xor_sync(0xffffffffu, c0, 16);
            c1 += __shfl_xor_sync(0xffffffffu, c1, 4);
            c1 += __shfl_xor_sync(0xffffffffu, c1, 8);
            c1 += __shfl_xor_sync(0xffffffffu, c1, 16);
            if ((lane >> 2) == 0) {
                const int col = n0 + wn + ni * 8 + (lane & 3) * 2;
                atomicAdd(&colsum[col], c0);
                atomicAdd(&colsum[col + 1], c1);
            }
        }
    }
}

// ====== conversions (also zeros the softmax-denominator buffers) ======
#define N4_X    ((size_t)Bq * Nq * Dq / 4)
#define N4_PHI  ((size_t)Dq * ESq / 4)
#define N4_W    ((size_t)Eq * Dq * Dq / 4)
#define N4_RS   ((size_t)Bq * Nq / 4)
#define N4_CS   ((size_t)Bq * ESq / 4)
#define N4_MAIN (N4_X + N4_PHI + N4_RS + N4_CS)

__global__ void convert_xphi_k(const float* __restrict__ x, const float* __restrict__ phi,
                               fp16* __restrict__ ox, fp16* __restrict__ ophi,
                               float* __restrict__ rowsum, float* __restrict__ colsum)
{
    size_t i = (size_t)blockIdx.x * blockDim.x + threadIdx.x;
    if (i >= N4_MAIN) return;
    if (i >= N4_X + N4_PHI) {
        i -= N4_X + N4_PHI;
        float4 z = make_float4(0.f, 0.f, 0.f, 0.f);
        if (i < N4_RS) reinterpret_cast<float4*>(rowsum)[i] = z;
        else           reinterpret_cast<float4*>(colsum)[i - N4_RS] = z;
        return;
    }
    const float* in; fp16* o;
    if (i < N4_X) { in = x; o = ox; }
    else          { i -= N4_X; in = phi; o = ophi; }
    const float4 v = reinterpret_cast<const float4*>(in)[i];
    reinterpret_cast<__half2*>(o)[2 * i] =
        __halves2half2(__float2half_rn(v.x), __float2half_rn(v.y));
    reinterpret_cast<__half2*>(o)[2 * i + 1] =
        __halves2half2(__float2half_rn(v.z), __float2half_rn(v.w));
}

__global__ void convert_W_k(const float* __restrict__ W1, const float* __restrict__ W2,
                            fp16* __restrict__ oW1, fp16* __restrict__ oW2)
{
    size_t i = (size_t)blockIdx.x * blockDim.x + threadIdx.x;
    if (i >= 2 * N4_W) return;
    const float* in; fp16* o;
    if (i < N4_W) { in = W1; o = oW1; }
    else          { i -= N4_W; in = W2; o = oW2; }
    const float4 v = reinterpret_cast<const float4*>(in)[i];
    reinterpret_cast<__half2*>(o)[2 * i] =
        __halves2half2(__float2half_rn(v.x), __float2half_rn(v.y));
    reinterpret_cast<__half2*>(o)[2 * i + 1] =
        __halves2half2(__float2half_rn(v.z), __float2half_rn(v.w));
}

// ====== pure fp16 transpose: e16 [N,ES] -> eT [ES,N], per batch ======
__global__ void transpose_k(const fp16* __restrict__ e16, fp16* __restrict__ eT)
{
    const int b = blockIdx.z, lane = threadIdx.x & 31, grp = threadIdx.x >> 5;
    const int col0 = blockIdx.x * 32;
    const int nbase = blockIdx.y * 256;
    const fp16* p = e16 + (size_t)b * Nq * ESq + col0;

    __shared__ fp16 t[32][40];

    const size_t obase = (size_t)b * ESq * Nq;
    for (int nc = 0; nc < 256; nc += 32) {
        const int n0 = nbase + nc;
#pragma unroll
        for (int i = 0; i < 4; i++) {
            const int r = grp * 4 + i;
            t[r][lane] = p[(size_t)(n0 + r) * ESq + lane];
        }
        __syncthreads();
#pragma unroll
        for (int i = 0; i < 4; i++) {
            const int cc = grp * 4 + i;
            eT[obase + (size_t)(col0 + cc) * Nq + n0 + lane] = t[lane][cc];
        }
        __syncthreads();
    }
}

// ===== LN + relu + residual over an expert range [eOff, eOff+8) =====
__global__ void ln_relu_k(const float* __restrict__ h,
                          const fp16* __restrict__ xh, const fp16* __restrict__ xl,
                          const float* __restrict__ g, const float* __restrict__ be,
                          fp16* __restrict__ oh, fp16* __restrict__ ol, int eOff)
{
    const int t = blockIdx.x;
    const int s = t % Sq;
    const int el = (t / Sq) & 7;
    const int b = t / (Sq * 8);
    const int e = eOff + el;
    const int r = (b * Eq + e) * Sq + s;
    const float* hr = h + (size_t)r * Dq;
    const int tid = threadIdx.x;
    __shared__ float rs[256], rs2[256];

    float v[4];
    float sm = 0.f, s2 = 0.f;
#pragma unroll
    for (int j = 0; j < 4; j++) {
        v[j] = hr[tid + 256 * j];
        sm += v[j]; s2 += v[j] * v[j];
    }
    rs[tid] = sm; rs2[tid] = s2;
    __syncthreads();
    for (int off = 128; off > 0; off >>= 1) {
        if (tid < off) { rs[tid] += rs[tid + off]; rs2[tid] += rs2[tid + off]; }
        __syncthreads();
    }
    const float mean = rs[0] * (1.f / Dq);
    const float var  = rs2[0] * (1.f / Dq) - mean * mean;
    const float rstd = rsqrtf(var + EPSq);

#pragma unroll
    for (int j = 0; j < 4; j++) {
        const int d = tid + 256 * j;
        const size_t o = (size_t)r * Dq + d;
        const float xr = __half2float(xh[o]) + __half2float(xl[o]);
        const float ln = (v[j] - mean) * rstd * g[(size_t)e * Dq + d] + be[(size_t)e * Dq + d];
        const float val = xr + fmaxf(ln, 0.f);
        fp16 hh = __float2half_rn(val);
        oh[o] = hh;
        ol[o] = __float2half_rn(val - __half2float(hh));
    }
}

// ================= launch =================
extern "C" void kernel_launch(void* const* d_in, const int* in_sizes, int n_in,
                              void* d_out, int out_size)
{
    const float* x   = (const float*)d_in[0];
    const float* phi = (const float*)d_in[1];
    const float* W1  = (const float*)d_in[2];
    const float* b1  = (const float*)d_in[3];
    const float* g1  = (const float*)d_in[4];
    const float* be1 = (const float*)d_in[5];
    const float* W2  = (const float*)d_in[6];
    const float* b2  = (const float*)d_in[7];
    float* out = (float*)d_out;

    static cudaStream_t s_side = nullptr;
    static cudaEvent_t eFork = nullptr, eW = nullptr;
    static cudaEvent_t eK4a = nullptr, eK4b = nullptr, eLnA = nullptr, eLnB = nullptr;
    if (s_side == nullptr) {
        cudaStreamCreateWithFlags(&s_side, cudaStreamNonBlocking);
        cudaEventCreateWithFlags(&eFork, cudaEventDisableTiming);
        cudaEventCreateWithFlags(&eW,    cudaEventDisableTiming);
        cudaEventCreateWithFlags(&eK4a,  cudaEventDisableTiming);
        cudaEventCreateWithFlags(&eK4b,  cudaEventDisableTiming);
        cudaEventCreateWithFlags(&eLnA,  cudaEventDisableTiming);
        cudaEventCreateWithFlags(&eLnB,  cudaEventDisableTiming);
        cudaFuncSetAttribute(mma_gemm_k<4,0,0>, cudaFuncAttributeMaxDynamicSharedMemorySize, SMEM_DYN);
        cudaFuncSetAttribute(mma_gemm_k<5,0,1>, cudaFuncAttributeMaxDynamicSharedMemorySize, SMEM_DYN);
        cudaFuncSetAttribute(mma_gemm_k<1,1,0>, cudaFuncAttributeMaxDynamicSharedMemorySize, SMEM_DYN);
        cudaFuncSetAttribute(mma_gemm_k<3,0,2>, cudaFuncAttributeMaxDynamicSharedMemorySize, SMEM_DYN);
        cudaFuncSetAttribute(mma_gemm_k<5,1,0>, cudaFuncAttributeMaxDynamicSharedMemorySize, SMEM_DYN);
    }

    float *h, *rowsum, *colsum;
    cudaGetSymbolAddress((void**)&h, g_h);
    cudaGetSymbolAddress((void**)&rowsum, g_rowsum);
    cudaGetSymbolAddress((void**)&colsum, g_colsum);

    fp16 *e16,*eT,*x16,*phi16,*W116,*W216,*xin_h,*xin_l,*x2_h,*x2_l,*y16;
    cudaGetSymbolAddress((void**)&e16, g_e16);
    cudaGetSymbolAddress((void**)&eT,  g_eT);
    cudaGetSymbolAddress((void**)&x16, g_x16);
    cudaGetSymbolAddress((void**)&phi16, g_phi16);
    cudaGetSymbolAddress((void**)&W116, g_W116);
    cudaGetSymbolAddress((void**)&W216, g_W216);
    cudaGetSymbolAddress((void**)&xin_h, g_xin_h); cudaGetSymbolAddress((void**)&xin_l, g_xin_l);
    cudaGetSymbolAddress((void**)&x2_h, g_x2_h);   cudaGetSymbolAddress((void**)&x2_l, g_x2_l);
    cudaGetSymbolAddress((void**)&y16, g_y16);

    const size_t EXP  = (size_t)Eq * Sq * Dq;   // batch stride
    const size_t HEXP = (size_t)8 * Sq * Dq;    // 8-expert offset within a batch

    // fork side stream: W conversion
    cudaEventRecord(eFork, 0);
    cudaStreamWaitEvent(s_side, eFork, 0);
    convert_W_k<<<(int)((2 * N4_W + 255) / 256), 256, 0, s_side>>>(W1, W2, W116, W216);
    cudaEventRecord(eW, s_side);

    // main: convert x/phi (+ zero denominators), K1 (exp epilogue)
    convert_xphi_k<<<(int)((N4_MAIN + 255) / 256), 256>>>(x, phi, x16, phi16, rowsum, colsum);

    mma_gemm_k<4,0,0><<<dim3(ESq/BN, Nq/BM, Bq), 256, SMEM_DYN>>>(
        x16, phi16, nullptr, nullptr, nullptr, nullptr, e16, nullptr,
        rowsum, colsum, 0,
        Dq, Dq, ESq, ESq,
        (size_t)Nq*Dq, 0, (size_t)Nq*ESq, 1, 0,
        (size_t)64*Dq, (size_t)64*ESq);

    transpose_k<<<dim3(ESq/32, Nq/256, Bq), 256>>>(e16, eT);

    // K3: xin = (eT @ x) / colsum[row]
    mma_gemm_k<5,0,1><<<dim3(Dq/BN, ESq/BM, Bq), 256, SMEM_DYN>>>(
        eT, x16, nullptr, nullptr, nullptr, nullptr, xin_h, xin_l,
        colsum, nullptr, (size_t)ESq,
        Nq, Nq, Dq, Dq,
        (size_t)ESq*Nq, (size_t)Nq*Dq, (size_t)ESq*Dq, Bq, 0,
        (size_t)64*Nq, (size_t)64*Dq);

    cudaStreamWaitEvent(0, eW, 0);

    // ---- expert section pipelined by halves (experts 0-7 = a, 8-15 = b) ----
    // K4a
    mma_gemm_k<1,1,0><<<dim3(Dq/BN, (Bq*Sq)/BM, 8), 256, SMEM_DYN>>>(
        xin_h, W116, b1, nullptr, nullptr, h, nullptr, nullptr,
        nullptr, nullptr, 0,
        Dq, Dq, Dq, Dq,
        (size_t)Sq*Dq, (size_t)Dq*Dq, (size_t)Sq*Dq, 8, (size_t)Dq,
        EXP, EXP);
    cudaEventRecord(eK4a, 0);

    // K4b
    mma_gemm_k<1,1,0><<<dim3(Dq/BN, (Bq*Sq)/BM, 8), 256, SMEM_DYN>>>(
        xin_h + HEXP, W116 + (size_t)8*Dq*Dq, b1 + (size_t)8*Dq, nullptr, nullptr,
        h + HEXP, nullptr, nullptr,
        nullptr, nullptr, 0,
        Dq, Dq, Dq, Dq,
        (size_t)Sq*Dq, (size_t)Dq*Dq, (size_t)Sq*Dq, 8, (size_t)Dq,
        EXP, EXP);
    cudaEventRecord(eK4b, 0);

    // side: lnA overlaps K4b; lnB overlaps K6a
    cudaStreamWaitEvent(s_side, eK4a, 0);
    ln_relu_k<<<Bq*8*Sq, 256, 0, s_side>>>(h, xin_h, xin_l, g1, be1, x2_h, x2_l, 0);
    cudaEventRecord(eLnA, s_side);
    cudaStreamWaitEvent(s_side, eK4b, 0);
    ln_relu_k<<<Bq*8*Sq, 256, 0, s_side>>>(h, xin_h, xin_l, g1, be1, x2_h, x2_l, 8);
    cudaEventRecord(eLnB, s_side);

    // K6a
    cudaStreamWaitEvent(0, eLnA, 0);
    mma_gemm_k<3,0,2><<<dim3(Dq/BN, (Bq*Sq)/BM, 8), 256, SMEM_DYN>>>(
        x2_h, W216, b2, x2_h, x2_l, nullptr, y16, nullptr,
        nullptr, nullptr, 0,
        Dq, Dq, Dq, Dq,
        (size_t)Sq*Dq, (size_t)Dq*Dq, (size_t)Sq*Dq, 8, (size_t)Dq,
        EXP, EXP);

    // K6b
    cudaStreamWaitEvent(0, eLnB, 0);
    mma_gemm_k<3,0,2><<<dim3(Dq/BN, (Bq*Sq)/BM, 8), 256, SMEM_DYN>>>(
        x2_h + HEXP, W216 + (size_t)8*Dq*Dq, b2 + (size_t)8*Dq, x2_h + HEXP, x2_l + HEXP,
        nullptr, y16 + HEXP, nullptr,
        nullptr, nullptr, 0,
        Dq, Dq, Dq, Dq,
        (size_t)Sq*Dq, (size_t)Dq*Dq, (size_t)Sq*Dq, 8, (size_t)Dq,
        EXP, EXP);

    // K8: out = (e16 @ y16) / rowsum[row]
    mma_gemm_k<5,1,0><<<dim3(Dq/BN, Nq/BM, Bq), 256, SMEM_DYN>>>(
        e16, y16, nullptr, nullptr, nullptr, out, nullptr, nullptr,
        rowsum, nullptr, (size_t)Nq,
        ESq, ESq, Dq, Dq,
        (size_t)Nq*ESq, EXP, (size_t)Nq*Dq, Bq, 0,
        (size_t)64*ESq, (size_t)64*Dq);
}